// round 6
// baseline (speedup 1.0000x reference)
#include <cuda_runtime.h>

// Problem constants
#define B_   8
#define C_   512
#define L_   2048
#define CQ_  64
#define KW_  3
#define KK_  (C_ * KW_)   // 1536 = im2col K for the convs

typedef unsigned long long u64;

// Packed f32x2 helpers (FFMA2 is unreachable from plain C++ — PTX only)
__device__ __forceinline__ u64 pack_dup(float a) {
    u64 r;
    asm("mov.b64 %0, {%1, %1};" : "=l"(r) : "f"(a));
    return r;
}
__device__ __forceinline__ void fma2(u64& d, u64 a, u64 b) {
    asm("fma.rn.f32x2 %0, %1, %2, %0;" : "+l"(d) : "l"(a), "l"(b));
}
__device__ __forceinline__ float2 unpack2(u64 v) {
    float2 f;
    asm("mov.b64 {%0, %1}, %2;" : "=f"(f.x), "=f"(f.y) : "l"(v));
    return f;
}

// Scratch (device globals — allocation-free)
static __device__ float g_q[B_ * CQ_ * L_];        // 4 MB
static __device__ float g_k[B_ * CQ_ * L_];        // 4 MB
static __device__ float g_v[B_ * C_ * L_];         // 33.5 MB
static __device__ float g_s[B_ * L_ * L_];         // 134 MB (scores, then beta in place)

// Shared 8x8 micro-tile FFMA2 inner product over a 16-deep k-tile.
// acc[i][jp] holds the (i, 2*jp..2*jp+1) pair of the micro-tile.
__device__ __forceinline__ void mma_tile_16(
    const float (*As)[128], const float (*Bs)[128],
    int tm, int tn, u64 acc[8][4])
{
#pragma unroll
    for (int kk2 = 0; kk2 < 16; kk2++) {
        // A broadcast values, duplicated into both f32x2 lanes
        float4 a0 = *(const float4*)&As[kk2][tm];
        float4 a1 = *(const float4*)&As[kk2][tm + 4];
        u64 ad[8];
        ad[0] = pack_dup(a0.x); ad[1] = pack_dup(a0.y);
        ad[2] = pack_dup(a0.z); ad[3] = pack_dup(a0.w);
        ad[4] = pack_dup(a1.x); ad[5] = pack_dup(a1.y);
        ad[6] = pack_dup(a1.z); ad[7] = pack_dup(a1.w);

        // B pairs, loaded directly as aligned 64-bit
        const u64* bp = (const u64*)&Bs[kk2][tn];
        u64 b0 = bp[0], b1 = bp[1], b2 = bp[2], b3 = bp[3];

#pragma unroll
        for (int i = 0; i < 8; i++) {
            fma2(acc[i][0], ad[i], b0);
            fma2(acc[i][1], ad[i], b1);
            fma2(acc[i][2], ad[i], b2);
            fma2(acc[i][3], ad[i], b3);
        }
    }
}

// ---------------------------------------------------------------------------
// Conv-as-implicit-GEMM: out[b, m, l] = sum_{c,t} W[m, c, t] * x[b, c, l+t-1]
// ---------------------------------------------------------------------------
__device__ __forceinline__ void conv_gemm_body(
    const float* __restrict__ x,
    const float* __restrict__ W0, const float* __restrict__ W1,
    float* __restrict__ out0, float* __restrict__ out1,
    int Msplit, int ostride)
{
    __shared__ float As[16][128];
    __shared__ float Bs[16][128];

    const int b  = blockIdx.z;
    const int l0 = blockIdx.x * 128;
    const int m0 = blockIdx.y * 128;
    const int tid = threadIdx.x;

    const int mloc = tid >> 1;
    const int half = tid & 1;
    const int mg   = m0 + mloc;
    const float* Arow = (mg < Msplit) ? (W0 + mg * KK_)
                                      : (W1 + (mg - Msplit) * KK_);
    Arow += half * 8;

    const int kr = tid >> 4;
    const int n0 = (tid & 15) * 8;
    const float* xb = x + b * C_ * L_;

    const int tm = (tid >> 4) * 8;
    const int tn = (tid & 15) * 8;

    u64 acc[8][4];
#pragma unroll
    for (int i = 0; i < 8; i++)
#pragma unroll
        for (int j = 0; j < 4; j++) acc[i][j] = 0ull;

    for (int k0 = 0; k0 < KK_; k0 += 16) {
        float4 a0 = *(const float4*)(Arow + k0);
        float4 a1 = *(const float4*)(Arow + k0 + 4);
        As[half * 8 + 0][mloc] = a0.x;
        As[half * 8 + 1][mloc] = a0.y;
        As[half * 8 + 2][mloc] = a0.z;
        As[half * 8 + 3][mloc] = a0.w;
        As[half * 8 + 4][mloc] = a1.x;
        As[half * 8 + 5][mloc] = a1.y;
        As[half * 8 + 6][mloc] = a1.z;
        As[half * 8 + 7][mloc] = a1.w;

        const int kk = k0 + kr;
        const int c  = kk / 3;
        const int t  = kk - c * 3;
        const float* xrow = xb + c * L_;
        const int base = l0 + n0 + t - 1;
#pragma unroll
        for (int j = 0; j < 8; j++) {
            const int gl = base + j;
            Bs[kr][n0 + j] = (gl >= 0 && gl < L_) ? xrow[gl] : 0.f;
        }
        __syncthreads();

        mma_tile_16(As, Bs, tm, tn, acc);
        __syncthreads();
    }

#pragma unroll
    for (int i = 0; i < 8; i++) {
        const int m = m0 + tm + i;
        float* orow = (m < Msplit) ? (out0 + b * ostride + m * L_)
                                   : (out1 + b * ostride + (m - Msplit) * L_);
        float2 p0 = unpack2(acc[i][0]);
        float2 p1 = unpack2(acc[i][1]);
        float2 p2 = unpack2(acc[i][2]);
        float2 p3 = unpack2(acc[i][3]);
        *(float4*)(orow + l0 + tn)     = make_float4(p0.x, p0.y, p1.x, p1.y);
        *(float4*)(orow + l0 + tn + 4) = make_float4(p2.x, p2.y, p3.x, p3.y);
    }
}

__global__ __launch_bounds__(256, 2) void conv_qk_kernel(
    const float* __restrict__ x, const float* __restrict__ Wq,
    const float* __restrict__ Wk)
{
    conv_gemm_body(x, Wq, Wk, g_q, g_k, CQ_, CQ_ * L_);
}

__global__ __launch_bounds__(256, 2) void conv_v_kernel(
    const float* __restrict__ x, const float* __restrict__ Wv)
{
    conv_gemm_body(x, Wv, Wv, g_v, g_v, 1 << 30, C_ * L_);
}

// ---------------------------------------------------------------------------
// scores[b, i, j] = sum_c q[b, c, i] * k[b, c, j]     (K = 64)
// ---------------------------------------------------------------------------
__global__ __launch_bounds__(256, 2) void scores_kernel()
{
    __shared__ float As[16][128];
    __shared__ float Bs[16][128];

    const int b  = blockIdx.z;
    const int j0 = blockIdx.x * 128;
    const int i0 = blockIdx.y * 128;
    const int tid = threadIdx.x;

    const int kc = tid >> 4;
    const int p0 = (tid & 15) * 8;
    const int tm = (tid >> 4) * 8;
    const int tn = (tid & 15) * 8;

    const float* qb = g_q + b * CQ_ * L_;
    const float* kb = g_k + b * CQ_ * L_;

    u64 acc[8][4];
#pragma unroll
    for (int i = 0; i < 8; i++)
#pragma unroll
        for (int j = 0; j < 4; j++) acc[i][j] = 0ull;

    for (int c0 = 0; c0 < CQ_; c0 += 16) {
        const float* qrow = qb + (c0 + kc) * L_ + i0 + p0;
        const float* krow = kb + (c0 + kc) * L_ + j0 + p0;
        *(float4*)&As[kc][p0]     = *(const float4*)(qrow);
        *(float4*)&As[kc][p0 + 4] = *(const float4*)(qrow + 4);
        *(float4*)&Bs[kc][p0]     = *(const float4*)(krow);
        *(float4*)&Bs[kc][p0 + 4] = *(const float4*)(krow + 4);
        __syncthreads();

        mma_tile_16(As, Bs, tm, tn, acc);
        __syncthreads();
    }

    float* sb = g_s + b * L_ * L_;
#pragma unroll
    for (int i = 0; i < 8; i++) {
        float* orow = sb + (i0 + tm + i) * L_ + j0 + tn;
        float2 p0 = unpack2(acc[i][0]);
        float2 p1 = unpack2(acc[i][1]);
        float2 p2 = unpack2(acc[i][2]);
        float2 p3 = unpack2(acc[i][3]);
        *(float4*)(orow)     = make_float4(p0.x, p0.y, p1.x, p1.y);
        *(float4*)(orow + 4) = make_float4(p2.x, p2.y, p3.x, p3.y);
    }
}

// ---------------------------------------------------------------------------
// In-place softmax over axis i (dim 1) of g_s[b, i, j].
// 32-column tiles, 8 i-groups per column -> 512 blocks for concurrency.
// ---------------------------------------------------------------------------
__global__ __launch_bounds__(256) void softmax_kernel()
{
    __shared__ float redm[256];
    __shared__ float reds[256];

    const int b  = blockIdx.y;
    const int j0 = blockIdx.x * 32;
    const int tid = threadIdx.x;
    const int jj = tid & 31;
    const int ig = tid >> 5;           // 0..7

    float* sb = g_s + b * L_ * L_ + j0 + jj;

    float m = -1e30f, s = 0.f;
    for (int i = ig; i < L_; i += 8) {
        const float v = sb[i * L_];
        const float nm = fmaxf(m, v);
        s = s * __expf(m - nm) + __expf(v - nm);
        m = nm;
    }
    redm[tid] = m;
    reds[tid] = s;
    __syncthreads();

    float M = -1e30f, S = 0.f;
#pragma unroll
    for (int g = 0; g < 8; g++) {
        const float mm = redm[g * 32 + jj];
        const float ss = reds[g * 32 + jj];
        const float nm = fmaxf(M, mm);
        S = S * __expf(M - nm) + ss * __expf(mm - nm);
        M = nm;
    }
    const float inv = 1.f / S;

    for (int i = ig; i < L_; i += 8) {
        const float v = sb[i * L_];
        sb[i * L_] = __expf(v - M) * inv;
    }
}

// ---------------------------------------------------------------------------
// out[b, c, j] = gamma * sum_l v[b, c, l] * beta[b, l, j]
// ---------------------------------------------------------------------------
__global__ __launch_bounds__(256, 2) void out_gemm_kernel(
    const float* __restrict__ gamma, float* __restrict__ out)
{
    __shared__ float As[16][128];
    __shared__ float Bs[16][128];

    const int b  = blockIdx.z;
    const int j0 = blockIdx.x * 128;
    const int c0 = blockIdx.y * 128;
    const int tid = threadIdx.x;

    const int mloc = tid >> 1;
    const int half = tid & 1;
    const float* Arow = g_v + b * C_ * L_ + (c0 + mloc) * L_ + half * 8;

    const int kr = tid >> 4;
    const int n0 = (tid & 15) * 8;
    const float* Bb = g_s + b * L_ * L_ + j0 + n0;

    const int tm = (tid >> 4) * 8;
    const int tn = (tid & 15) * 8;

    u64 acc[8][4];
#pragma unroll
    for (int i = 0; i < 8; i++)
#pragma unroll
        for (int j = 0; j < 4; j++) acc[i][j] = 0ull;

    for (int k0 = 0; k0 < L_; k0 += 16) {
        float4 a0 = *(const float4*)(Arow + k0);
        float4 a1 = *(const float4*)(Arow + k0 + 4);
        As[half * 8 + 0][mloc] = a0.x;
        As[half * 8 + 1][mloc] = a0.y;
        As[half * 8 + 2][mloc] = a0.z;
        As[half * 8 + 3][mloc] = a0.w;
        As[half * 8 + 4][mloc] = a1.x;
        As[half * 8 + 5][mloc] = a1.y;
        As[half * 8 + 6][mloc] = a1.z;
        As[half * 8 + 7][mloc] = a1.w;

        const float* brow = Bb + (k0 + kr) * L_;
        *(float4*)&Bs[kr][n0]     = *(const float4*)(brow);
        *(float4*)&Bs[kr][n0 + 4] = *(const float4*)(brow + 4);
        __syncthreads();

        mma_tile_16(As, Bs, tm, tn, acc);
        __syncthreads();
    }

    const float g = __ldg(gamma);
#pragma unroll
    for (int i = 0; i < 8; i++) {
        float* orow = out + b * C_ * L_ + (c0 + tm + i) * L_ + j0 + tn;
        float2 p0 = unpack2(acc[i][0]);
        float2 p1 = unpack2(acc[i][1]);
        float2 p2 = unpack2(acc[i][2]);
        float2 p3 = unpack2(acc[i][3]);
        *(float4*)(orow)     = make_float4(g * p0.x, g * p0.y, g * p1.x, g * p1.y);
        *(float4*)(orow + 4) = make_float4(g * p2.x, g * p2.y, g * p3.x, g * p3.y);
    }
}

// ---------------------------------------------------------------------------
extern "C" void kernel_launch(void* const* d_in, const int* in_sizes, int n_in,
                              void* d_out, int out_size)
{
    const float* x     = (const float*)d_in[0];
    const float* Wq    = (const float*)d_in[1];
    const float* Wk    = (const float*)d_in[2];
    const float* Wv    = (const float*)d_in[3];
    const float* gamma = (const float*)d_in[4];
    float* out = (float*)d_out;

    dim3 blk(256);

    conv_qk_kernel<<<dim3(L_ / 128, 1, B_), blk>>>(x, Wq, Wk);
    conv_v_kernel<<<dim3(L_ / 128, C_ / 128, B_), blk>>>(x, Wv);
    scores_kernel<<<dim3(L_ / 128, L_ / 128, B_), blk>>>();
    softmax_kernel<<<dim3(L_ / 32, B_), blk>>>();
    out_gemm_kernel<<<dim3(L_ / 128, C_ / 128, B_), blk>>>(gamma, out);
}

// round 8
// speedup vs baseline: 2.9740x; 2.9740x over previous
#include <cuda_runtime.h>

// Problem constants
#define B_   8
#define C_   512
#define L_   2048
#define CQ_  64
#define KK_  1536          // im2col K for the convs (512*3)

// Scratch (device globals — allocation-free)
static __device__ float g_q[B_ * CQ_ * L_];
static __device__ float g_k[B_ * CQ_ * L_];
static __device__ float g_v[B_ * C_ * L_];
static __device__ float g_s[B_ * L_ * L_];

// SMEM layout (bytes, dynamic):
//   A_hi @ 0      A_lo @ 10240    (NT layout: 128 rows x 80B;  T layout: 32 rows x 272B)
//   B_hi @ 20480  B_lo @ 29184    (always T layout: 32 k-rows x 272B)
#define SA_STRIDE_NT 80u
#define ST_STRIDE    272u
#define OFF_ALO  10240u
#define OFF_BHI  20480u
#define OFF_BLO  29184u
#define SMEM_SZ  37888

// ---------------------------------------------------------------------------
// PTX helpers
// ---------------------------------------------------------------------------
static __device__ __forceinline__ void ldsm4(unsigned r[4], unsigned addr) {
    asm volatile("ldmatrix.sync.aligned.m8n8.x4.shared.b16 {%0,%1,%2,%3}, [%4];"
                 : "=r"(r[0]), "=r"(r[1]), "=r"(r[2]), "=r"(r[3]) : "r"(addr));
}
static __device__ __forceinline__ void ldsm4t(unsigned r[4], unsigned addr) {
    asm volatile("ldmatrix.sync.aligned.m8n8.x4.trans.shared.b16 {%0,%1,%2,%3}, [%4];"
                 : "=r"(r[0]), "=r"(r[1]), "=r"(r[2]), "=r"(r[3]) : "r"(addr));
}
static __device__ __forceinline__ void mma16816(float d[4], const unsigned a[4],
                                                unsigned b0, unsigned b1) {
    asm volatile(
        "mma.sync.aligned.m16n8k16.row.col.f32.bf16.bf16.f32 "
        "{%0,%1,%2,%3}, {%4,%5,%6,%7}, {%8,%9}, {%0,%1,%2,%3};"
        : "+f"(d[0]), "+f"(d[1]), "+f"(d[2]), "+f"(d[3])
        : "r"(a[0]), "r"(a[1]), "r"(a[2]), "r"(a[3]), "r"(b0), "r"(b1));
}

// Split fp32 pair -> hi (top-16 truncation, packed via PRMT) + lo (rn bf16 of
// the exact residual), store both as one b32 each.
static __device__ __forceinline__ void split_store(unsigned shi, unsigned slo,
                                                   unsigned off, float a0, float a1) {
    unsigned b0 = __float_as_uint(a0), b1 = __float_as_uint(a1);
    unsigned uhi;
    asm("prmt.b32 %0, %1, %2, 0x7632;" : "=r"(uhi) : "r"(b0), "r"(b1));
    float h0 = __uint_as_float(b0 & 0xffff0000u);
    float h1 = __uint_as_float(b1 & 0xffff0000u);
    float l0 = a0 - h0, l1 = a1 - h1;
    unsigned ulo;
    asm("cvt.rn.bf16x2.f32 %0, %1, %2;" : "=r"(ulo) : "f"(l1), "f"(l0));
    asm volatile("st.shared.b32 [%0], %1;" :: "r"(shi + off), "r"(uhi));
    asm volatile("st.shared.b32 [%0], %1;" :: "r"(slo + off), "r"(ulo));
}

// NT A-tile loader: this thread owns row m, k-half kh (0/16); src points at the
// 16 contiguous fp32 source values.
static __device__ __forceinline__ void loadA_NT(unsigned shi, unsigned slo,
                                                const float* __restrict__ src,
                                                int m, int kh) {
    const unsigned base = (unsigned)m * SA_STRIDE_NT + (unsigned)kh * 2u;
#pragma unroll
    for (int q = 0; q < 4; q++) {
        float4 f = ((const float4*)src)[q];
        split_store(shi, slo, base + 8u * q,      f.x, f.y);
        split_store(shi, slo, base + 8u * q + 4u, f.z, f.w);
    }
}

// T tile loader (k-major layout): thread owns k-row kc, column offset c0 (16 wide);
// src points at 16 contiguous fp32 values along the column dim.
static __device__ __forceinline__ void loadT(unsigned shi, unsigned slo,
                                             const float* __restrict__ src,
                                             int kc, int c0) {
    const unsigned base = (unsigned)kc * ST_STRIDE + (unsigned)c0 * 2u;
#pragma unroll
    for (int q = 0; q < 4; q++) {
        float4 f = ((const float4*)src)[q];
        split_store(shi, slo, base + 8u * q,      f.x, f.y);
        split_store(shi, slo, base + 8u * q + 4u, f.z, f.w);
    }
}

// Conv im2col B loader (T layout): tile element (k=kc, n) = x[c, l0+n+t-1],
// (c,t) = divmod(k0+kc, 3). Thread owns k-row kc, 16 consecutive n.
static __device__ __forceinline__ void loadB_conv(unsigned shi, unsigned slo,
                                                  const float* __restrict__ xb,
                                                  int k0, int l0, int tid) {
    const int kc = tid >> 3, n0 = (tid & 7) * 16;
    const int kA = k0 + kc;
    const int c  = kA / 3;
    const int t  = kA - 3 * c;
    const float* xr = xb + c * L_;
    const int p = l0 + n0 + t - 1;
    float v[16];
#pragma unroll
    for (int i = 0; i < 16; i++)
        v[i] = ((unsigned)(p + i) < (unsigned)L_) ? xr[p + i] : 0.f;
    const unsigned base = (unsigned)kc * ST_STRIDE + (unsigned)n0 * 2u;
#pragma unroll
    for (int i = 0; i < 8; i++)
        split_store(shi, slo, base + 4u * i, v[2 * i], v[2 * i + 1]);
}

// ---------------------------------------------------------------------------
// Per-problem parameter structs
// ---------------------------------------------------------------------------
struct PConvQK {                 // M=128 (q rows 0-63 | k rows 64-127), K=1536
    const float *x, *Wq, *Wk;
    static constexpr int NCH = KK_ / 32;
    static constexpr bool A_T = false;
    __device__ void load(unsigned ahi, unsigned alo, unsigned bhi, unsigned blo,
                         int ch, int tid) const {
        const int b = blockIdx.z, l0 = blockIdx.x * 128, k0 = ch * 32;
        const int m = tid >> 1, kh = (tid & 1) * 16;
        const float* w = (m < CQ_) ? (Wq + m * KK_) : (Wk + (m - CQ_) * KK_);
        loadA_NT(ahi, alo, w + k0 + kh, m, kh);
        loadB_conv(bhi, blo, x + b * C_ * L_, k0, l0, tid);
    }
    __device__ float* orow(int m) const {
        const int b = blockIdx.z, l0 = blockIdx.x * 128;
        return (m < CQ_) ? (g_q + (b * CQ_ + m) * L_ + l0)
                         : (g_k + (b * CQ_ + m - CQ_) * L_ + l0);
    }
    __device__ float scale() const { return 1.f; }
};

struct PConvV {                  // M=512 tiled by 128, K=1536
    const float *x, *Wv;
    static constexpr int NCH = KK_ / 32;
    static constexpr bool A_T = false;
    __device__ void load(unsigned ahi, unsigned alo, unsigned bhi, unsigned blo,
                         int ch, int tid) const {
        const int b = blockIdx.z, l0 = blockIdx.x * 128, c0 = blockIdx.y * 128;
        const int k0 = ch * 32;
        const int m = tid >> 1, kh = (tid & 1) * 16;
        loadA_NT(ahi, alo, Wv + (c0 + m) * KK_ + k0 + kh, m, kh);
        loadB_conv(bhi, blo, x + b * C_ * L_, k0, l0, tid);
    }
    __device__ float* orow(int m) const {
        const int b = blockIdx.z, l0 = blockIdx.x * 128, c0 = blockIdx.y * 128;
        return g_v + (b * C_ + c0 + m) * L_ + l0;
    }
    __device__ float scale() const { return 1.f; }
};

struct PScores {                 // D[i,j] = sum_c q[c,i]*k[c,j], K=64
    static constexpr int NCH = CQ_ / 32;
    static constexpr bool A_T = true;        // q is k-major -> T layout + ldsm.trans
    __device__ void load(unsigned ahi, unsigned alo, unsigned bhi, unsigned blo,
                         int ch, int tid) const {
        const int b = blockIdx.z, j0 = blockIdx.x * 128, i0 = blockIdx.y * 128;
        const int k0 = ch * 32;
        const int kc = tid >> 3, c0 = (tid & 7) * 16;
        loadT(ahi, alo, g_q + (b * CQ_ + k0 + kc) * L_ + i0 + c0, kc, c0);
        loadT(bhi, blo, g_k + (b * CQ_ + k0 + kc) * L_ + j0 + c0, kc, c0);
    }
    __device__ float* orow(int m) const {
        const int b = blockIdx.z, j0 = blockIdx.x * 128, i0 = blockIdx.y * 128;
        return g_s + (size_t)b * L_ * L_ + (size_t)(i0 + m) * L_ + j0;
    }
    __device__ float scale() const { return 1.f; }
};

struct POut {                    // out[c,j] = gamma * sum_l v[c,l]*beta[l,j], K=2048
    const float* gamma;
    float* out;
    static constexpr int NCH = L_ / 32;
    static constexpr bool A_T = false;
    __device__ void load(unsigned ahi, unsigned alo, unsigned bhi, unsigned blo,
                         int ch, int tid) const {
        const int b = blockIdx.z, j0 = blockIdx.x * 128, c0 = blockIdx.y * 128;
        const int k0 = ch * 32;
        const int m = tid >> 1, kh = (tid & 1) * 16;
        loadA_NT(ahi, alo, g_v + (b * C_ + c0 + m) * L_ + k0 + kh, m, kh);
        const int kc = tid >> 3, n0 = (tid & 7) * 16;
        loadT(bhi, blo, g_s + (size_t)b * L_ * L_ + (size_t)(k0 + kc) * L_ + j0 + n0,
              kc, n0);
    }
    __device__ float* orow(int m) const {
        const int b = blockIdx.z, j0 = blockIdx.x * 128, c0 = blockIdx.y * 128;
        return out + (size_t)(b * C_ + c0 + m) * L_ + j0;
    }
    __device__ float scale() const { return __ldg(gamma); }
};

// ---------------------------------------------------------------------------
// Generic mma.sync bf16-split GEMM core: 128x128 CTA tile, 8 warps (2x4),
// 64x32 warp tile, K-chunk 32, 3-term hi/lo split for fp32 accuracy.
// ---------------------------------------------------------------------------
template <class P>
__global__ __launch_bounds__(256, 2) void mma_kernel(P prm)
{
    extern __shared__ __align__(16) char smem[];
    const unsigned sb = (unsigned)__cvta_generic_to_shared(smem);
    const unsigned ahi = sb, alo = sb + OFF_ALO;
    const unsigned bhi = sb + OFF_BHI, blo = sb + OFF_BLO;

    const int tid  = threadIdx.x;
    const int lane = tid & 31;
    const int wid  = tid >> 5;
    const int wm   = wid >> 2;          // 0..1 (m)
    const int wn   = wid & 3;           // 0..3 (n)

    float acc[4][4][4];
#pragma unroll
    for (int a = 0; a < 4; a++)
#pragma unroll
        for (int b = 0; b < 4; b++)
#pragma unroll
            for (int c = 0; c < 4; c++) acc[a][b][c] = 0.f;

    // Lane address components
    const unsigned mNT   = (unsigned)((lane & 7) + ((lane >> 3) & 1) * 8);  // row within m16
    const unsigned ksegNT = (unsigned)(((lane >> 4) & 1) * 16);             // k-half bytes
    const unsigned krowT  = (unsigned)(((lane >> 4) & 1) * 8 + (lane & 7)); // k-row within k16
    const unsigned chalfT = (unsigned)(((lane >> 3) & 1) * 8);              // col-half

    for (int ch = 0; ch < P::NCH; ch++) {
        __syncthreads();
        prm.load(ahi, alo, bhi, blo, ch, tid);
        __syncthreads();

#pragma unroll
        for (int ks = 0; ks < 2; ks++) {
            // --- A hi fragments (4 m16-tiles) ---
            unsigned af[4][4];
#pragma unroll
            for (int mi = 0; mi < 4; mi++) {
                if (P::A_T) {
                    const unsigned kb = ((unsigned)(ks * 16) + krowT) * ST_STRIDE;
                    const unsigned col = ((unsigned)(wm * 64 + mi * 16) + chalfT) * 2u;
                    ldsm4t(af[mi], ahi + kb + col);
                } else {
                    const unsigned row = (unsigned)(wm * 64 + mi * 16) + mNT;
                    ldsm4(af[mi], ahi + row * SA_STRIDE_NT + (unsigned)(ks * 32) + ksegNT);
                }
            }
            // --- B hi / lo fragments (2 x n16) ---
            unsigned bhf[2][4], blf[2][4];
            const unsigned kbB = ((unsigned)(ks * 16) + krowT) * ST_STRIDE;
#pragma unroll
            for (int ni2 = 0; ni2 < 2; ni2++) {
                const unsigned col = ((unsigned)(wn * 32 + ni2 * 16) + chalfT) * 2u;
                ldsm4t(bhf[ni2], bhi + kbB + col);
                ldsm4t(blf[ni2], blo + kbB + col);
            }
            // hi*hi + hi*lo
#pragma unroll
            for (int mi = 0; mi < 4; mi++)
#pragma unroll
                for (int ni2 = 0; ni2 < 2; ni2++) {
                    mma16816(acc[mi][2 * ni2],     af[mi], bhf[ni2][0], bhf[ni2][2]);
                    mma16816(acc[mi][2 * ni2 + 1], af[mi], bhf[ni2][1], bhf[ni2][3]);
                    mma16816(acc[mi][2 * ni2],     af[mi], blf[ni2][0], blf[ni2][2]);
                    mma16816(acc[mi][2 * ni2 + 1], af[mi], blf[ni2][1], blf[ni2][3]);
                }
            // lo*hi (reload A as lo, reuse B hi)
#pragma unroll
            for (int mi = 0; mi < 4; mi++) {
                unsigned al[4];
                if (P::A_T) {
                    const unsigned kb = ((unsigned)(ks * 16) + krowT) * ST_STRIDE;
                    const unsigned col = ((unsigned)(wm * 64 + mi * 16) + chalfT) * 2u;
                    ldsm4t(al, alo + kb + col);
                } else {
                    const unsigned row = (unsigned)(wm * 64 + mi * 16) + mNT;
                    ldsm4(al, alo + row * SA_STRIDE_NT + (unsigned)(ks * 32) + ksegNT);
                }
#pragma unroll
                for (int ni2 = 0; ni2 < 2; ni2++) {
                    mma16816(acc[mi][2 * ni2],     al, bhf[ni2][0], bhf[ni2][2]);
                    mma16816(acc[mi][2 * ni2 + 1], al, bhf[ni2][1], bhf[ni2][3]);
                }
            }
        }
    }

    // Epilogue: d-frag rows l>>2 (+8), cols 2*(l&3) (+1)
    const float s = prm.scale();
#pragma unroll
    for (int mi = 0; mi < 4; mi++) {
        const int r0 = wm * 64 + mi * 16 + (lane >> 2);
#pragma unroll
        for (int rr = 0; rr < 2; rr++) {
            float* row = prm.orow(r0 + rr * 8);
#pragma unroll
            for (int ni = 0; ni < 4; ni++) {
                const int col = wn * 32 + ni * 8 + (lane & 3) * 2;
                float2 v;
                v.x = acc[mi][ni][2 * rr]     * s;
                v.y = acc[mi][ni][2 * rr + 1] * s;
                *(float2*)(row + col) = v;
            }
        }
    }
}

// ---------------------------------------------------------------------------
// In-place softmax over axis i of g_s[b, i, j] (measured 103 us)
// ---------------------------------------------------------------------------
__global__ __launch_bounds__(256) void softmax_kernel()
{
    __shared__ float redm[256];
    __shared__ float reds[256];

    const int b  = blockIdx.y;
    const int j0 = blockIdx.x * 32;
    const int tid = threadIdx.x;
    const int jj = tid & 31;
    const int ig = tid >> 5;

    float* sbp = g_s + (size_t)b * L_ * L_ + j0 + jj;

    float m = -1e30f, s = 0.f;
    for (int i = ig; i < L_; i += 8) {
        const float v = sbp[(size_t)i * L_];
        const float nm = fmaxf(m, v);
        s = s * __expf(m - nm) + __expf(v - nm);
        m = nm;
    }
    redm[tid] = m;
    reds[tid] = s;
    __syncthreads();

    float M = -1e30f, S = 0.f;
#pragma unroll
    for (int g = 0; g < 8; g++) {
        const float mm = redm[g * 32 + jj];
        const float ss = reds[g * 32 + jj];
        const float nm = fmaxf(M, mm);
        S = S * __expf(M - nm) + ss * __expf(mm - nm);
        M = nm;
    }
    const float inv = 1.f / S;

    for (int i = ig; i < L_; i += 8) {
        const float v = sbp[(size_t)i * L_];
        sbp[(size_t)i * L_] = __expf(v - M) * inv;
    }
}

// ---------------------------------------------------------------------------
extern "C" void kernel_launch(void* const* d_in, const int* in_sizes, int n_in,
                              void* d_out, int out_size)
{
    const float* x     = (const float*)d_in[0];
    const float* Wq    = (const float*)d_in[1];
    const float* Wk    = (const float*)d_in[2];
    const float* Wv    = (const float*)d_in[3];
    const float* gamma = (const float*)d_in[4];
    float* out = (float*)d_out;

    dim3 blk(256);

    mma_kernel<PConvQK><<<dim3(L_ / 128, 1, B_),        blk, SMEM_SZ>>>(PConvQK{x, Wq, Wk});
    mma_kernel<PConvV> <<<dim3(L_ / 128, C_ / 128, B_), blk, SMEM_SZ>>>(PConvV{x, Wv});
    mma_kernel<PScores><<<dim3(L_ / 128, L_ / 128, B_), blk, SMEM_SZ>>>(PScores{});
    softmax_kernel     <<<dim3(L_ / 32, B_),            blk>>>();
    mma_kernel<POut>   <<<dim3(L_ / 128, C_ / 128, B_), blk, SMEM_SZ>>>(POut{gamma, out});
}

// round 9
// speedup vs baseline: 3.2820x; 1.1036x over previous
#include <cuda_runtime.h>

// Problem constants
#define B_   8
#define C_   512
#define L_   2048
#define CQ_  64
#define KK_  1536          // im2col K for the convs (512*3)

// Scratch (device globals — allocation-free)
static __device__ float g_q[B_ * CQ_ * L_];
static __device__ float g_k[B_ * CQ_ * L_];
static __device__ float g_v[B_ * C_ * L_];
static __device__ float g_s[B_ * L_ * L_];

// SMEM buffer layout (bytes within one buffer):
//   A_hi @ 0      A_lo @ 10240    (NT: 128 rows x 80B; T: 32 rows x 272B)
//   B_hi @ 20480  B_lo @ 29184    (always T: 32 k-rows x 272B)
#define SA_STRIDE 80u
#define ST_STRIDE 272u
#define OFF_ALO  10240u
#define OFF_BHI  20480u
#define OFF_BLO  29184u
#define BUF_SZ   37888u
#define SMEM_SZ  (2 * 37888)

// ---------------------------------------------------------------------------
// PTX helpers
// ---------------------------------------------------------------------------
static __device__ __forceinline__ void ldsm4(unsigned r[4], unsigned addr) {
    asm volatile("ldmatrix.sync.aligned.m8n8.x4.shared.b16 {%0,%1,%2,%3}, [%4];"
                 : "=r"(r[0]), "=r"(r[1]), "=r"(r[2]), "=r"(r[3]) : "r"(addr));
}
static __device__ __forceinline__ void ldsm4t(unsigned r[4], unsigned addr) {
    asm volatile("ldmatrix.sync.aligned.m8n8.x4.trans.shared.b16 {%0,%1,%2,%3}, [%4];"
                 : "=r"(r[0]), "=r"(r[1]), "=r"(r[2]), "=r"(r[3]) : "r"(addr));
}
static __device__ __forceinline__ void mma16816(float d[4], const unsigned a[4],
                                                unsigned b0, unsigned b1) {
    asm volatile(
        "mma.sync.aligned.m16n8k16.row.col.f32.bf16.bf16.f32 "
        "{%0,%1,%2,%3}, {%4,%5,%6,%7}, {%8,%9}, {%0,%1,%2,%3};"
        : "+f"(d[0]), "+f"(d[1]), "+f"(d[2]), "+f"(d[3])
        : "r"(a[0]), "r"(a[1]), "r"(a[2]), "r"(a[3]), "r"(b0), "r"(b1));
}

// Split fp32 pair -> hi (top-16 truncation via PRMT) + lo (rn bf16 of residual)
static __device__ __forceinline__ void split_pack(float a0, float a1,
                                                  unsigned& h, unsigned& l) {
    unsigned b0 = __float_as_uint(a0), b1 = __float_as_uint(a1);
    asm("prmt.b32 %0, %1, %2, 0x7632;" : "=r"(h) : "r"(b0), "r"(b1));
    float h0 = __uint_as_float(b0 & 0xffff0000u);
    float h1 = __uint_as_float(b1 & 0xffff0000u);
    asm("cvt.rn.bf16x2.f32 %0, %1, %2;" : "=r"(l) : "f"(a1 - h1), "f"(a0 - h0));
}

// Split 16 consecutive values and store hi/lo tiles with 2x st.shared.v4 each.
static __device__ __forceinline__ void sts16(unsigned shi, unsigned slo,
                                             unsigned base, const float* v) {
    unsigned h[8], l[8];
#pragma unroll
    for (int i = 0; i < 8; i++) split_pack(v[2 * i], v[2 * i + 1], h[i], l[i]);
    asm volatile("st.shared.v4.b32 [%0], {%1,%2,%3,%4};"
                 :: "r"(shi + base),      "r"(h[0]), "r"(h[1]), "r"(h[2]), "r"(h[3]));
    asm volatile("st.shared.v4.b32 [%0], {%1,%2,%3,%4};"
                 :: "r"(shi + base + 16), "r"(h[4]), "r"(h[5]), "r"(h[6]), "r"(h[7]));
    asm volatile("st.shared.v4.b32 [%0], {%1,%2,%3,%4};"
                 :: "r"(slo + base),      "r"(l[0]), "r"(l[1]), "r"(l[2]), "r"(l[3]));
    asm volatile("st.shared.v4.b32 [%0], {%1,%2,%3,%4};"
                 :: "r"(slo + base + 16), "r"(l[4]), "r"(l[5]), "r"(l[6]), "r"(l[7]));
}

static __device__ __forceinline__ void ldg16(const float* __restrict__ p, float* v) {
#pragma unroll
    for (int q = 0; q < 4; q++) *(float4*)(v + 4 * q) = ((const float4*)p)[q];
}

// ---------------------------------------------------------------------------
// Per-problem parameter structs: ldg (global->regs) and sts (split->smem)
// ---------------------------------------------------------------------------
static __device__ __forceinline__ void ldgB_conv(const float* __restrict__ x,
                                                 int k0, int l0, int tid, float* bv) {
    const int kc = tid >> 3, n0 = (tid & 7) * 16;
    const int kA = k0 + kc, c = kA / 3, t = kA - 3 * c;
    const float* xr = x + c * L_;
    const int p = l0 + n0 + t - 1;
#pragma unroll
    for (int i = 0; i < 16; i++)
        bv[i] = ((unsigned)(p + i) < (unsigned)L_) ? xr[p + i] : 0.f;
}

struct PConvQK {                 // M=128 (q rows 0-63 | k rows 64-127), K=1536
    const float *x, *Wq, *Wk;
    static constexpr int NCH = KK_ / 32;
    static constexpr bool A_T = false;
    __device__ void ldg(int ch, int tid, float* a, float* bv) const {
        const int b = blockIdx.z, l0 = blockIdx.x * 128, k0 = ch * 32;
        const int m = tid >> 1, kh = (tid & 1) * 16;
        const float* w = (m < CQ_) ? (Wq + m * KK_) : (Wk + (m - CQ_) * KK_);
        ldg16(w + k0 + kh, a);
        ldgB_conv(x + b * C_ * L_, k0, l0, tid, bv);
    }
    __device__ void sts(unsigned buf, int tid, const float* a, const float* bv) const {
        const int m = tid >> 1, kh = (tid & 1) * 16;
        sts16(buf, buf + OFF_ALO, (unsigned)(m * 80 + kh * 2), a);
        const int kc = tid >> 3, n0 = (tid & 7) * 16;
        sts16(buf + OFF_BHI, buf + OFF_BLO, (unsigned)(kc * 272 + n0 * 2), bv);
    }
    __device__ float* orow(int m) const {
        const int b = blockIdx.z, l0 = blockIdx.x * 128;
        return (m < CQ_) ? (g_q + (b * CQ_ + m) * L_ + l0)
                         : (g_k + (b * CQ_ + m - CQ_) * L_ + l0);
    }
    __device__ float scale() const { return 1.f; }
};

struct PConvV {                  // M=512 tiled by 128, K=1536
    const float *x, *Wv;
    static constexpr int NCH = KK_ / 32;
    static constexpr bool A_T = false;
    __device__ void ldg(int ch, int tid, float* a, float* bv) const {
        const int b = blockIdx.z, l0 = blockIdx.x * 128, c0 = blockIdx.y * 128;
        const int k0 = ch * 32;
        const int m = tid >> 1, kh = (tid & 1) * 16;
        ldg16(Wv + (c0 + m) * KK_ + k0 + kh, a);
        ldgB_conv(x + b * C_ * L_, k0, l0, tid, bv);
    }
    __device__ void sts(unsigned buf, int tid, const float* a, const float* bv) const {
        const int m = tid >> 1, kh = (tid & 1) * 16;
        sts16(buf, buf + OFF_ALO, (unsigned)(m * 80 + kh * 2), a);
        const int kc = tid >> 3, n0 = (tid & 7) * 16;
        sts16(buf + OFF_BHI, buf + OFF_BLO, (unsigned)(kc * 272 + n0 * 2), bv);
    }
    __device__ float* orow(int m) const {
        const int b = blockIdx.z, l0 = blockIdx.x * 128, c0 = blockIdx.y * 128;
        return g_v + (b * C_ + c0 + m) * L_ + l0;
    }
    __device__ float scale() const { return 1.f; }
};

struct PScores {                 // D[i,j] = sum_c q[c,i]*k[c,j], K=64
    static constexpr int NCH = CQ_ / 32;
    static constexpr bool A_T = true;
    __device__ void ldg(int ch, int tid, float* a, float* bv) const {
        const int b = blockIdx.z, j0 = blockIdx.x * 128, i0 = blockIdx.y * 128;
        const int k0 = ch * 32;
        const int kc = tid >> 3, c0 = (tid & 7) * 16;
        ldg16(g_q + (b * CQ_ + k0 + kc) * L_ + i0 + c0, a);
        ldg16(g_k + (b * CQ_ + k0 + kc) * L_ + j0 + c0, bv);
    }
    __device__ void sts(unsigned buf, int tid, const float* a, const float* bv) const {
        const int kc = tid >> 3, c0 = (tid & 7) * 16;
        const unsigned base = (unsigned)(kc * 272 + c0 * 2);
        sts16(buf, buf + OFF_ALO, base, a);
        sts16(buf + OFF_BHI, buf + OFF_BLO, base, bv);
    }
    __device__ float* orow(int m) const {
        const int b = blockIdx.z, j0 = blockIdx.x * 128, i0 = blockIdx.y * 128;
        return g_s + (size_t)b * L_ * L_ + (size_t)(i0 + m) * L_ + j0;
    }
    __device__ float scale() const { return 1.f; }
};

struct POut {                    // out[c,j] = gamma * sum_l v[c,l]*beta[l,j], K=2048
    const float* gamma;
    float* out;
    static constexpr int NCH = L_ / 32;
    static constexpr bool A_T = false;
    __device__ void ldg(int ch, int tid, float* a, float* bv) const {
        const int b = blockIdx.z, j0 = blockIdx.x * 128, c0 = blockIdx.y * 128;
        const int k0 = ch * 32;
        const int m = tid >> 1, kh = (tid & 1) * 16;
        ldg16(g_v + (b * C_ + c0 + m) * L_ + k0 + kh, a);
        const int kc = tid >> 3, n0 = (tid & 7) * 16;
        ldg16(g_s + (size_t)b * L_ * L_ + (size_t)(k0 + kc) * L_ + j0 + n0, bv);
    }
    __device__ void sts(unsigned buf, int tid, const float* a, const float* bv) const {
        const int m = tid >> 1, kh = (tid & 1) * 16;
        sts16(buf, buf + OFF_ALO, (unsigned)(m * 80 + kh * 2), a);
        const int kc = tid >> 3, n0 = (tid & 7) * 16;
        sts16(buf + OFF_BHI, buf + OFF_BLO, (unsigned)(kc * 272 + n0 * 2), bv);
    }
    __device__ float* orow(int m) const {
        const int b = blockIdx.z, j0 = blockIdx.x * 128, c0 = blockIdx.y * 128;
        return out + (size_t)(b * C_ + c0 + m) * L_ + j0;
    }
    __device__ float scale() const { return __ldg(gamma); }
};

// ---------------------------------------------------------------------------
// Double-buffered mma.sync bf16-split GEMM core: 128x128 CTA tile, 8 warps,
// 64x32 warp tile, K-chunk 32, 3-term hi/lo split.
// ---------------------------------------------------------------------------
template <class P>
__global__ __launch_bounds__(256, 2) void mma_kernel(P prm)
{
    extern __shared__ __align__(16) char smem[];
    const unsigned sb = (unsigned)__cvta_generic_to_shared(smem);

    const int tid  = threadIdx.x;
    const int lane = tid & 31;
    const int wid  = tid >> 5;
    const int wm   = wid >> 2;          // 0..1 (m)
    const int wn   = wid & 3;           // 0..3 (n)

    float acc[4][4][4];
#pragma unroll
    for (int a = 0; a < 4; a++)
#pragma unroll
        for (int b = 0; b < 4; b++)
#pragma unroll
            for (int c = 0; c < 4; c++) acc[a][b][c] = 0.f;

    const unsigned mNT    = (unsigned)((lane & 7) + ((lane >> 3) & 1) * 8);
    const unsigned ksel   = (unsigned)((lane >> 4) & 1);
    const unsigned krowT  = (unsigned)(ksel * 8 + (lane & 7));
    const unsigned chalfT = (unsigned)(((lane >> 3) & 1) * 8);

    // Prologue: stage chunk 0 -> smem buf0, stage chunk 1 in regs.
    float sa[16], sv[16];
    prm.ldg(0, tid, sa, sv);
    prm.sts(sb, tid, sa, sv);
    if (P::NCH > 1) prm.ldg(1, tid, sa, sv);
    __syncthreads();

    for (int ch = 0; ch < P::NCH; ch++) {
        const unsigned base = sb + (unsigned)(ch & 1) * BUF_SZ;

#pragma unroll
        for (int ks = 0; ks < 2; ks++) {
            // B hi/lo fragments (2 x n16), hoisted for this k16 step
            unsigned bh[2][4], bl[2][4];
            const unsigned kbB = ((unsigned)(ks * 16) + krowT) * ST_STRIDE;
#pragma unroll
            for (int n2 = 0; n2 < 2; n2++) {
                const unsigned col = ((unsigned)(wn * 32 + n2 * 16) + chalfT) * 2u;
                ldsm4t(bh[n2], base + OFF_BHI + kbB + col);
                ldsm4t(bl[n2], base + OFF_BLO + kbB + col);
            }
#pragma unroll
            for (int mi = 0; mi < 4; mi++) {
                unsigned a4[4];
                if (P::A_T) {
                    const unsigned kb  = ((unsigned)(ks * 16) + krowT) * ST_STRIDE;
                    const unsigned col = ((unsigned)(wm * 64 + mi * 16) + chalfT) * 2u;
                    ldsm4t(a4, base + kb + col);
                } else {
                    const unsigned row = (unsigned)(wm * 64 + mi * 16) + mNT;
                    ldsm4(a4, base + row * SA_STRIDE + (unsigned)(ks * 32) + ksel * 16u);
                }
#pragma unroll
                for (int n2 = 0; n2 < 2; n2++) {
                    mma16816(acc[mi][2 * n2],     a4, bh[n2][0], bh[n2][2]);
                    mma16816(acc[mi][2 * n2 + 1], a4, bh[n2][1], bh[n2][3]);
                    mma16816(acc[mi][2 * n2],     a4, bl[n2][0], bl[n2][2]);
                    mma16816(acc[mi][2 * n2 + 1], a4, bl[n2][1], bl[n2][3]);
                }
                if (P::A_T) {
                    const unsigned kb  = ((unsigned)(ks * 16) + krowT) * ST_STRIDE;
                    const unsigned col = ((unsigned)(wm * 64 + mi * 16) + chalfT) * 2u;
                    ldsm4t(a4, base + OFF_ALO + kb + col);
                } else {
                    const unsigned row = (unsigned)(wm * 64 + mi * 16) + mNT;
                    ldsm4(a4, base + OFF_ALO + row * SA_STRIDE + (unsigned)(ks * 32) + ksel * 16u);
                }
#pragma unroll
                for (int n2 = 0; n2 < 2; n2++) {
                    mma16816(acc[mi][2 * n2],     a4, bh[n2][0], bh[n2][2]);
                    mma16816(acc[mi][2 * n2 + 1], a4, bh[n2][1], bh[n2][3]);
                }
            }
        }

        // Stage chunk ch+1 into the other buffer (safe: last read of it was
        // iteration ch-1, protected by that iteration's barrier).
        if (ch + 1 < P::NCH)
            prm.sts(sb + (unsigned)((ch + 1) & 1) * BUF_SZ, tid, sa, sv);
        __syncthreads();
        // Prefetch chunk ch+2 (consumed by sts at iteration ch+1 -> latency
        // hidden behind a full MMA phase).
        if (ch + 2 < P::NCH) prm.ldg(ch + 2, tid, sa, sv);
    }

    // Epilogue: d-frag rows lane>>2 (+8), cols 2*(lane&3) (+1)
    const float s = prm.scale();
#pragma unroll
    for (int mi = 0; mi < 4; mi++) {
        const int r0 = wm * 64 + mi * 16 + (lane >> 2);
#pragma unroll
        for (int rr = 0; rr < 2; rr++) {
            float* row = prm.orow(r0 + rr * 8);
#pragma unroll
            for (int ni = 0; ni < 4; ni++) {
                const int col = wn * 32 + ni * 8 + (lane & 3) * 2;
                float2 v;
                v.x = acc[mi][ni][2 * rr]     * s;
                v.y = acc[mi][ni][2 * rr + 1] * s;
                *(float2*)(row + col) = v;
            }
        }
    }
}

// ---------------------------------------------------------------------------
// In-place softmax over axis i of g_s[b, i, j]; 2-way ILP unroll.
// ---------------------------------------------------------------------------
__global__ __launch_bounds__(256) void softmax_kernel()
{
    __shared__ float redm[256];
    __shared__ float reds[256];

    const int b  = blockIdx.y;
    const int j0 = blockIdx.x * 32;
    const int tid = threadIdx.x;
    const int jj = tid & 31;
    const int ig = tid >> 5;

    float* sbp = g_s + (size_t)b * L_ * L_ + j0 + jj;

    float m0 = -1e30f, s0 = 0.f, m1 = -1e30f, s1 = 0.f;
    for (int i = ig; i < L_; i += 16) {
        const float v0 = sbp[(size_t)i * L_];
        const float v1 = sbp[(size_t)(i + 8) * L_];
        float nm = fmaxf(m0, v0);
        s0 = s0 * __expf(m0 - nm) + __expf(v0 - nm);
        m0 = nm;
        nm = fmaxf(m1, v1);
        s1 = s1 * __expf(m1 - nm) + __expf(v1 - nm);
        m1 = nm;
    }
    {
        const float nm = fmaxf(m0, m1);
        s0 = s0 * __expf(m0 - nm) + s1 * __expf(m1 - nm);
        m0 = nm;
    }
    redm[tid] = m0;
    reds[tid] = s0;
    __syncthreads();

    float M = -1e30f, S = 0.f;
#pragma unroll
    for (int g = 0; g < 8; g++) {
        const float mm = redm[g * 32 + jj];
        const float ss = reds[g * 32 + jj];
        const float nm = fmaxf(M, mm);
        S = S * __expf(M - nm) + ss * __expf(mm - nm);
        M = nm;
    }
    const float inv = 1.f / S;

    for (int i = ig; i < L_; i += 16) {
        const float v0 = sbp[(size_t)i * L_];
        const float v1 = sbp[(size_t)(i + 8) * L_];
        sbp[(size_t)i * L_]       = __expf(v0 - M) * inv;
        sbp[(size_t)(i + 8) * L_] = __expf(v1 - M) * inv;
    }
}

// ---------------------------------------------------------------------------
extern "C" void kernel_launch(void* const* d_in, const int* in_sizes, int n_in,
                              void* d_out, int out_size)
{
    const float* x     = (const float*)d_in[0];
    const float* Wq    = (const float*)d_in[1];
    const float* Wk    = (const float*)d_in[2];
    const float* Wv    = (const float*)d_in[3];
    const float* gamma = (const float*)d_in[4];
    float* out = (float*)d_out;

    // Dynamic smem > 48 KB requires explicit opt-in (host-side attr, capture-safe)
    cudaFuncSetAttribute(mma_kernel<PConvQK>,
                         cudaFuncAttributeMaxDynamicSharedMemorySize, SMEM_SZ);
    cudaFuncSetAttribute(mma_kernel<PConvV>,
                         cudaFuncAttributeMaxDynamicSharedMemorySize, SMEM_SZ);
    cudaFuncSetAttribute(mma_kernel<PScores>,
                         cudaFuncAttributeMaxDynamicSharedMemorySize, SMEM_SZ);
    cudaFuncSetAttribute(mma_kernel<POut>,
                         cudaFuncAttributeMaxDynamicSharedMemorySize, SMEM_SZ);

    dim3 blk(256);

    mma_kernel<PConvQK><<<dim3(L_ / 128, 1, B_),        blk, SMEM_SZ>>>(PConvQK{x, Wq, Wk});
    mma_kernel<PConvV> <<<dim3(L_ / 128, C_ / 128, B_), blk, SMEM_SZ>>>(PConvV{x, Wv});
    mma_kernel<PScores><<<dim3(L_ / 128, L_ / 128, B_), blk, SMEM_SZ>>>(PScores{});
    softmax_kernel     <<<dim3(L_ / 32, B_),            blk>>>();
    mma_kernel<POut>   <<<dim3(L_ / 128, C_ / 128, B_), blk, SMEM_SZ>>>(POut{gamma, out});
}

// round 11
// speedup vs baseline: 3.3900x; 1.0329x over previous
#include <cuda_runtime.h>

// Problem constants
#define B_   8
#define C_   512
#define L_   2048
#define CQ_  64
#define KK_  1536

typedef unsigned short u16;
typedef unsigned int   u32;

// ---------------------------------------------------------------------------
// Scratch (device globals — allocation-free). 16B-aligned for cp.async.
// ---------------------------------------------------------------------------
static __device__ __align__(16) u16 xsh_hi[3][B_ * C_ * L_];
static __device__ __align__(16) u16 xsh_lo[3][B_ * C_ * L_];
static __device__ __align__(16) u16 wqk_hi[3 * 128 * 512];   // [t][m][c], q|k rows
static __device__ __align__(16) u16 wqk_lo[3 * 128 * 512];
static __device__ __align__(16) u16 wv_hi[3 * 512 * 512];    // [t][m][c]
static __device__ __align__(16) u16 wv_lo[3 * 512 * 512];
static __device__ __align__(16) u16 q_hi[B_ * CQ_ * L_], q_lo[B_ * CQ_ * L_];
static __device__ __align__(16) u16 k_hi[B_ * CQ_ * L_], k_lo[B_ * CQ_ * L_];
static __device__ __align__(16) u16 v_hi[B_ * C_ * L_],  v_lo[B_ * C_ * L_];
static __device__ float g_s[B_ * L_ * L_];                   // scores (fp32)
static __device__ __align__(16) u16 b_hi[B_ * L_ * L_], b_lo[B_ * L_ * L_];

// SMEM buffer layout (per buffer):
//   A_hi @ 0      A_lo @ 10240    (NT: 128 rows x 80B; T: 32 rows x 272B)
//   B_hi @ 20480  B_lo @ 29184    (T: 32 k-rows x 272B)
#define SA_STRIDE 80u
#define ST_STRIDE 272u
#define OFF_ALO  10240u
#define OFF_BHI  20480u
#define OFF_BLO  29184u
#define BLO_DELTA 8704u          // OFF_BLO - OFF_BHI
#define BUF_SZ   37888u
#define SMEM_SZ  (2 * 37888)

// ---------------------------------------------------------------------------
// PTX helpers
// ---------------------------------------------------------------------------
static __device__ __forceinline__ void ldsm4(unsigned r[4], unsigned addr) {
    asm volatile("ldmatrix.sync.aligned.m8n8.x4.shared.b16 {%0,%1,%2,%3}, [%4];"
                 : "=r"(r[0]), "=r"(r[1]), "=r"(r[2]), "=r"(r[3]) : "r"(addr));
}
static __device__ __forceinline__ void ldsm4t(unsigned r[4], unsigned addr) {
    asm volatile("ldmatrix.sync.aligned.m8n8.x4.trans.shared.b16 {%0,%1,%2,%3}, [%4];"
                 : "=r"(r[0]), "=r"(r[1]), "=r"(r[2]), "=r"(r[3]) : "r"(addr));
}
static __device__ __forceinline__ void mma16816(float d[4], const unsigned a[4],
                                                unsigned b0, unsigned b1) {
    asm volatile(
        "mma.sync.aligned.m16n8k16.row.col.f32.bf16.bf16.f32 "
        "{%0,%1,%2,%3}, {%4,%5,%6,%7}, {%8,%9}, {%0,%1,%2,%3};"
        : "+f"(d[0]), "+f"(d[1]), "+f"(d[2]), "+f"(d[3])
        : "r"(a[0]), "r"(a[1]), "r"(a[2]), "r"(a[3]), "r"(b0), "r"(b1));
}
static __device__ __forceinline__ void cpa16(unsigned s, const void* g) {
    asm volatile("cp.async.cg.shared.global [%0], [%1], 16;" :: "r"(s), "l"(g));
}
#define CP_COMMIT() asm volatile("cp.async.commit_group;" ::: "memory")
static __device__ __forceinline__ void cp_wait1() {
    asm volatile("cp.async.wait_group 1;" ::: "memory");
}
static __device__ __forceinline__ void cp_wait0() {
    asm volatile("cp.async.wait_group 0;" ::: "memory");
}

// fp32 pair -> hi (top-16 truncation) + lo (rn bf16 of exact residual)
static __device__ __forceinline__ void split_pack(float a0, float a1, u32& h, u32& l) {
    u32 b0 = __float_as_uint(a0), b1 = __float_as_uint(a1);
    asm("prmt.b32 %0, %1, %2, 0x7632;" : "=r"(h) : "r"(b0), "r"(b1));
    float h0 = __uint_as_float(b0 & 0xffff0000u);
    float h1 = __uint_as_float(b1 & 0xffff0000u);
    asm("cvt.rn.bf16x2.f32 %0, %1, %2;" : "=r"(l) : "f"(a1 - h1), "f"(a0 - h0));
}
static __device__ __forceinline__ void pack8(const float* v, uint4& H, uint4& L) {
    u32 h[4], l[4];
#pragma unroll
    for (int i = 0; i < 4; i++) split_pack(v[2 * i], v[2 * i + 1], h[i], l[i]);
    H = make_uint4(h[0], h[1], h[2], h[3]);
    L = make_uint4(l[0], l[1], l[2], l[3]);
}
// fp32 pair -> (hi bf16x2 via rn, lo bf16x2 of residual)
static __device__ __forceinline__ void split_rn(float2 v, u32& h, u32& l) {
    asm("cvt.rn.bf16x2.f32 %0, %1, %2;" : "=r"(h) : "f"(v.y), "f"(v.x));
    float hx = __uint_as_float(h << 16);
    float hy = __uint_as_float(h & 0xffff0000u);
    asm("cvt.rn.bf16x2.f32 %0, %1, %2;" : "=r"(l) : "f"(v.y - hy), "f"(v.x - hx));
}

// ---------------------------------------------------------------------------
// Prep kernels
// ---------------------------------------------------------------------------
__global__ __launch_bounds__(256) void prep_x(const float* __restrict__ x)
{
    const int idx = blockIdx.x * 256 + threadIdx.x;      // over B*C*L/8
    const int base = idx * 8;
    const int row = base >> 11;                          // b*C + c
    const int l = base & (L_ - 1);
    const float* xr = x + (size_t)row * L_;

    float v[10];
    *(float4*)(v + 1) = *(const float4*)(xr + l);
    *(float4*)(v + 5) = *(const float4*)(xr + l + 4);
    v[0] = (l > 0) ? xr[l - 1] : 0.f;
    v[9] = (l + 8 < L_) ? xr[l + 8] : 0.f;

    const size_t o = (size_t)row * L_ + l;
#pragma unroll
    for (int t = 0; t < 3; t++) {        // xsh[t][j] = x[j + t - 1]
        uint4 H, L;
        pack8(v + t, H, L);
        *(uint4*)(&xsh_hi[t][o]) = H;
        *(uint4*)(&xsh_lo[t][o]) = L;
    }
}

__global__ __launch_bounds__(256) void prep_wqk(const float* __restrict__ Wq,
                                                const float* __restrict__ Wk)
{
    const int idx = blockIdx.x * 256 + threadIdx.x;      // 3*128*64
    const int c8 = idx & 63, m = (idx >> 6) & 127, t = idx >> 13;
    const float* src = ((m < CQ_) ? (Wq + m * KK_) : (Wk + (m - CQ_) * KK_)) + c8 * 24 + t;
    float v[8];
#pragma unroll
    for (int i = 0; i < 8; i++) v[i] = src[i * 3];
    uint4 H, L;
    pack8(v, H, L);
    const int o = (t * 128 + m) * 512 + c8 * 8;
    *(uint4*)(&wqk_hi[o]) = H;
    *(uint4*)(&wqk_lo[o]) = L;
}

__global__ __launch_bounds__(256) void prep_wv(const float* __restrict__ Wv)
{
    const int idx = blockIdx.x * 256 + threadIdx.x;      // 3*512*64
    const int c8 = idx & 63, m = (idx >> 6) & 511, t = idx >> 15;
    const float* src = Wv + m * KK_ + c8 * 24 + t;
    float v[8];
#pragma unroll
    for (int i = 0; i < 8; i++) v[i] = src[i * 3];
    uint4 H, L;
    pack8(v, H, L);
    const int o = (t * 512 + m) * 512 + c8 * 8;
    *(uint4*)(&wv_hi[o]) = H;
    *(uint4*)(&wv_lo[o]) = L;
}

// ---------------------------------------------------------------------------
// cp.async tile issue helpers
// ---------------------------------------------------------------------------
// NT A tile: 128 rows x 32 k. Thread: row=tid>>1, seg=tid&1 (32B each).
static __device__ __forceinline__ void cpA_NT(unsigned buf, int tid,
                                              const u16* hi, const u16* lo,
                                              size_t rstride) {
    const int m = tid >> 1, s = tid & 1;
    const unsigned sm = buf + (unsigned)m * SA_STRIDE + (unsigned)s * 32u;
    const size_t go = (size_t)m * rstride + s * 16;
    cpa16(sm,                 hi + go);  cpa16(sm + 16u,            hi + go + 8);
    cpa16(sm + OFF_ALO,       lo + go);  cpa16(sm + OFF_ALO + 16u,  lo + go + 8);
}
// T tile: 32 k-rows x 128 cols. Thread: row=tid>>3, seg=tid&7 (32B each).
// ldelta = smem byte distance from hi tile to lo tile (A: OFF_ALO, B: BLO_DELTA).
static __device__ __forceinline__ void cpT(unsigned buf, int tid,
                                           const u16* hi, const u16* lo,
                                           size_t rstride, unsigned ldelta) {
    const int kc = tid >> 3, s = tid & 7;
    const unsigned sm = buf + (unsigned)kc * ST_STRIDE + (unsigned)s * 32u;
    const size_t go = (size_t)kc * rstride + s * 16;
    cpa16(sm,                hi + go);  cpa16(sm + 16u,           hi + go + 8);
    cpa16(sm + ldelta,       lo + go);  cpa16(sm + ldelta + 16u,  lo + go + 8);
}

// ---------------------------------------------------------------------------
// Per-problem structs
// ---------------------------------------------------------------------------
struct PConvQK {                 // M=128 (q|k), K=1536 as [t=3][c=512]
    static constexpr int NCH = 48;
    static constexpr bool A_T = false;
    __device__ void issue(unsigned buf, int ch, int tid) const {
        const int b = blockIdx.z, l0 = blockIdx.x * 128;
        const int t = ch >> 4, c0 = (ch & 15) * 32;
        cpA_NT(buf, tid, wqk_hi + (t * 128) * 512 + c0,
                         wqk_lo + (t * 128) * 512 + c0, 512);
        const size_t bo = ((size_t)(b * C_ + c0)) * L_ + l0;
        cpT(buf + OFF_BHI, tid, xsh_hi[t] + bo, xsh_lo[t] + bo, L_, BLO_DELTA);
    }
    __device__ float scale() const { return 1.f; }
    __device__ void store2(int m, int col, float2 v) const {
        const int b = blockIdx.z, l0 = blockIdx.x * 128;
        const size_t off = ((size_t)(b * CQ_ + (m & 63))) * L_ + l0 + col;
        u32 h, l;
        split_rn(v, h, l);
        if (m < CQ_) { *(u32*)(q_hi + off) = h; *(u32*)(q_lo + off) = l; }
        else         { *(u32*)(k_hi + off) = h; *(u32*)(k_lo + off) = l; }
    }
};

struct PConvV {                  // M=512 (by 128), K=1536 as [t][c]
    static constexpr int NCH = 48;
    static constexpr bool A_T = false;
    __device__ void issue(unsigned buf, int ch, int tid) const {
        const int b = blockIdx.z, l0 = blockIdx.x * 128, m0 = blockIdx.y * 128;
        const int t = ch >> 4, c0 = (ch & 15) * 32;
        cpA_NT(buf, tid, wv_hi + (t * 512 + m0) * 512 + c0,
                         wv_lo + (t * 512 + m0) * 512 + c0, 512);
        const size_t bo = ((size_t)(b * C_ + c0)) * L_ + l0;
        cpT(buf + OFF_BHI, tid, xsh_hi[t] + bo, xsh_lo[t] + bo, L_, BLO_DELTA);
    }
    __device__ float scale() const { return 1.f; }
    __device__ void store2(int m, int col, float2 v) const {
        const int b = blockIdx.z, l0 = blockIdx.x * 128, m0 = blockIdx.y * 128;
        const size_t off = ((size_t)(b * C_ + m0 + m)) * L_ + l0 + col;
        u32 h, l;
        split_rn(v, h, l);
        *(u32*)(v_hi + off) = h;
        *(u32*)(v_lo + off) = l;
    }
};

struct PScores {                 // D[i,j] = sum_c q[c,i]*k[c,j], K=64
    static constexpr int NCH = 2;
    static constexpr bool A_T = true;
    __device__ void issue(unsigned buf, int ch, int tid) const {
        const int b = blockIdx.z, j0 = blockIdx.x * 128, i0 = blockIdx.y * 128;
        const size_t ao = ((size_t)(b * CQ_ + ch * 32)) * L_ + i0;
        cpT(buf,           tid, q_hi + ao, q_lo + ao, L_, OFF_ALO);    // A: lo @ +10240
        const size_t bo = ((size_t)(b * CQ_ + ch * 32)) * L_ + j0;
        cpT(buf + OFF_BHI, tid, k_hi + bo, k_lo + bo, L_, BLO_DELTA);  // B: lo @ +8704
    }
    __device__ float scale() const { return 1.f; }
    __device__ void store2(int m, int col, float2 v) const {
        const int b = blockIdx.z, j0 = blockIdx.x * 128, i0 = blockIdx.y * 128;
        float* row = g_s + (size_t)b * L_ * L_ + (size_t)(i0 + m) * L_ + j0;
        *(float2*)(row + col) = v;
    }
};

struct POut {                    // out[c,j] = gamma * sum_l v[c,l]*beta[l,j], K=2048
    const float* gamma;
    float* out;
    static constexpr int NCH = 64;
    static constexpr bool A_T = false;
    __device__ void issue(unsigned buf, int ch, int tid) const {
        const int b = blockIdx.z, j0 = blockIdx.x * 128, c0 = blockIdx.y * 128;
        const size_t ao = ((size_t)(b * C_ + c0)) * L_ + ch * 32;
        cpA_NT(buf, tid, v_hi + ao, v_lo + ao, L_);
        const size_t bo = ((size_t)b * L_ + ch * 32) * L_ + j0;
        cpT(buf + OFF_BHI, tid, b_hi + bo, b_lo + bo, L_, BLO_DELTA);
    }
    __device__ float scale() const { return __ldg(gamma); }
    __device__ void store2(int m, int col, float2 v) const {
        const int b = blockIdx.z, j0 = blockIdx.x * 128, c0 = blockIdx.y * 128;
        float* row = out + ((size_t)(b * C_ + c0 + m)) * L_ + j0;
        *(float2*)(row + col) = v;
    }
};

// ---------------------------------------------------------------------------
// cp.async-pipelined mma.sync bf16-split GEMM core: 128x128 CTA tile, 8 warps,
// 64x32 warp tile, K-chunk 32, 3-term hi/lo split.
// ---------------------------------------------------------------------------
template <class P>
__global__ __launch_bounds__(256, 2) void mma_kernel(P prm)
{
    extern __shared__ __align__(16) char smem[];
    const unsigned sb = (unsigned)__cvta_generic_to_shared(smem);

    const int tid  = threadIdx.x;
    const int lane = tid & 31;
    const int wid  = tid >> 5;
    const int wm   = wid >> 2;
    const int wn   = wid & 3;

    float acc[4][4][4];
#pragma unroll
    for (int a = 0; a < 4; a++)
#pragma unroll
        for (int b = 0; b < 4; b++)
#pragma unroll
            for (int c = 0; c < 4; c++) acc[a][b][c] = 0.f;

    const unsigned mNT    = (unsigned)((lane & 7) + ((lane >> 3) & 1) * 8);
    const unsigned ksel   = (unsigned)((lane >> 4) & 1);
    const unsigned krowT  = (unsigned)(ksel * 8 + (lane & 7));
    const unsigned chalfT = (unsigned)(((lane >> 3) & 1) * 8);

    // Prologue: stage chunks 0 and 1.
    prm.issue(sb, 0, tid);
    CP_COMMIT();
    if (P::NCH > 1) { prm.issue(sb + BUF_SZ, 1, tid); CP_COMMIT(); cp_wait1(); }
    else cp_wait0();
    __syncthreads();

    for (int ch = 0; ch < P::NCH; ch++) {
        const unsigned base = sb + (unsigned)(ch & 1) * BUF_SZ;

#pragma unroll
        for (int ks = 0; ks < 2; ks++) {
            unsigned bh[2][4], bl[2][4];
            const unsigned kbB = ((unsigned)(ks * 16) + krowT) * ST_STRIDE;
#pragma unroll
            for (int n2 = 0; n2 < 2; n2++) {
                const unsigned col = ((unsigned)(wn * 32 + n2 * 16) + chalfT) * 2u;
                ldsm4t(bh[n2], base + OFF_BHI + kbB + col);
                ldsm4t(bl[n2], base + OFF_BLO + kbB + col);
            }
#pragma unroll
            for (int mi = 0; mi < 4; mi++) {
                unsigned a4[4];
                if (P::A_T) {
                    const unsigned kb  = ((unsigned)(ks * 16) + krowT) * ST_STRIDE;
                    const unsigned col = ((unsigned)(wm * 64 + mi * 16) + chalfT) * 2u;
                    ldsm4t(a4, base + kb + col);
                } else {
                    const unsigned row = (unsigned)(wm * 64 + mi * 16) + mNT;
                    ldsm4(a4, base + row * SA_STRIDE + (unsigned)(ks * 32) + ksel * 16u);
                }
#pragma unroll
                for (int n2 = 0; n2 < 2; n2++) {
                    mma16816(acc[mi][2 * n2],     a4, bh[n2][0], bh[n2][2]);
                    mma16816(acc[mi][2 * n2 + 1], a4, bh[n2][1], bh[n2][3]);
                    mma16816(acc[mi][2 * n2],     a4, bl[n2][0], bl[n2][2]);
                    mma16816(acc[mi][2 * n2 + 1], a4, bl[n2][1], bl[n2][3]);
                }
                if (P::A_T) {
                    const unsigned kb  = ((unsigned)(ks * 16) + krowT) * ST_STRIDE;
                    const unsigned col = ((unsigned)(wm * 64 + mi * 16) + chalfT) * 2u;
                    ldsm4t(a4, base + OFF_ALO + kb + col);
                } else {
                    const unsigned row = (unsigned)(wm * 64 + mi * 16) + mNT;
                    ldsm4(a4, base + OFF_ALO + row * SA_STRIDE + (unsigned)(ks * 32) + ksel * 16u);
                }
#pragma unroll
                for (int n2 = 0; n2 < 2; n2++) {
                    mma16816(acc[mi][2 * n2],     a4, bh[n2][0], bh[n2][2]);
                    mma16816(acc[mi][2 * n2 + 1], a4, bh[n2][1], bh[n2][3]);
                }
            }
        }

        __syncthreads();                    // all warps done reading buf[ch&1]
        if (ch + 2 < P::NCH) { prm.issue(base, ch + 2, tid); CP_COMMIT(); }
        if (ch + 1 < P::NCH) {
            if (ch + 2 < P::NCH) cp_wait1(); else cp_wait0();
            __syncthreads();                // buf[(ch+1)&1] fully landed
        }
    }

    const float s = prm.scale();
#pragma unroll
    for (int mi = 0; mi < 4; mi++) {
#pragma unroll
        for (int rr = 0; rr < 2; rr++) {
            const int r = wm * 64 + mi * 16 + (lane >> 2) + rr * 8;
#pragma unroll
            for (int ni = 0; ni < 4; ni++) {
                const int col = wn * 32 + ni * 8 + (lane & 3) * 2;
                float2 v;
                v.x = acc[mi][ni][2 * rr]     * s;
                v.y = acc[mi][ni][2 * rr + 1] * s;
                prm.store2(r, col, v);
            }
        }
    }
}

// ---------------------------------------------------------------------------
// Softmax over axis i of g_s[b, i, j]; writes beta as bf16 hi/lo.
// ---------------------------------------------------------------------------
__global__ __launch_bounds__(256) void softmax_kernel()
{
    __shared__ float redm[256];
    __shared__ float reds[256];

    const int b  = blockIdx.y;
    const int j0 = blockIdx.x * 32;
    const int tid = threadIdx.x;
    const int jj = tid & 31;
    const int ig = tid >> 5;

    const size_t cb = (size_t)b * L_ * L_ + j0 + jj;
    const float* sbp = g_s + cb;

    float m0 = -1e30f, s0 = 0.f, m1 = -1e30f, s1 = 0.f;
    for (int i = ig; i < L_; i += 16) {
        const float v0 = sbp[(size_t)i * L_];
        const float v1 = sbp[(size_t)(i + 8) * L_];
        float nm = fmaxf(m0, v0);
        s0 = s0 * __expf(m0 - nm) + __expf(v0 - nm);
        m0 = nm;
        nm = fmaxf(m1, v1);
        s1 = s1 * __expf(m1 - nm) + __expf(v1 - nm);
        m1 = nm;
    }
    {
        const float nm = fmaxf(m0, m1);
        s0 = s0 * __expf(m0 - nm) + s1 * __expf(m1 - nm);
        m0 = nm;
    }
    redm[tid] = m0;
    reds[tid] = s0;
    __syncthreads();

    float M = -1e30f, S = 0.f;
#pragma unroll
    for (int g = 0; g < 8; g++) {
        const float mm = redm[g * 32 + jj];
        const float ss = reds[g * 32 + jj];
        const float nm = fmaxf(M, mm);
        S = S * __expf(M - nm) + ss * __expf(mm - nm);
        M = nm;
    }
    const float inv = 1.f / S;

    for (int i = ig; i < L_; i += 16) {
#pragma unroll
        for (int u = 0; u < 2; u++) {
            const size_t idx = cb + (size_t)(i + u * 8) * L_;
            const float val = __expf(g_s[idx] - M) * inv;
            u16 hs;
            asm("cvt.rn.bf16.f32 %0, %1;" : "=h"(hs) : "f"(val));
            const float hf = __uint_as_float((u32)hs << 16);
            u16 ls;
            asm("cvt.rn.bf16.f32 %0, %1;" : "=h"(ls) : "f"(val - hf));
            b_hi[idx] = hs;
            b_lo[idx] = ls;
        }
    }
}

// ---------------------------------------------------------------------------
extern "C" void kernel_launch(void* const* d_in, const int* in_sizes, int n_in,
                              void* d_out, int out_size)
{
    const float* x     = (const float*)d_in[0];
    const float* Wq    = (const float*)d_in[1];
    const float* Wk    = (const float*)d_in[2];
    const float* Wv    = (const float*)d_in[3];
    const float* gamma = (const float*)d_in[4];
    float* out = (float*)d_out;

    cudaFuncSetAttribute(mma_kernel<PConvQK>,
                         cudaFuncAttributeMaxDynamicSharedMemorySize, SMEM_SZ);
    cudaFuncSetAttribute(mma_kernel<PConvV>,
                         cudaFuncAttributeMaxDynamicSharedMemorySize, SMEM_SZ);
    cudaFuncSetAttribute(mma_kernel<PScores>,
                         cudaFuncAttributeMaxDynamicSharedMemorySize, SMEM_SZ);
    cudaFuncSetAttribute(mma_kernel<POut>,
                         cudaFuncAttributeMaxDynamicSharedMemorySize, SMEM_SZ);

    dim3 blk(256);

    prep_x  <<<B_ * C_ * L_ / 8 / 256, blk>>>(x);
    prep_wqk<<<3 * 128 * 64 / 256,     blk>>>(Wq, Wk);
    prep_wv <<<3 * 512 * 64 / 256,     blk>>>(Wv);

    mma_kernel<PConvQK><<<dim3(L_ / 128, 1, B_),        blk, SMEM_SZ>>>(PConvQK{});
    mma_kernel<PConvV> <<<dim3(L_ / 128, C_ / 128, B_), blk, SMEM_SZ>>>(PConvV{});
    mma_kernel<PScores><<<dim3(L_ / 128, L_ / 128, B_), blk, SMEM_SZ>>>(PScores{});
    softmax_kernel     <<<dim3(L_ / 32, B_),            blk>>>();
    mma_kernel<POut>   <<<dim3(L_ / 128, C_ / 128, B_), blk, SMEM_SZ>>>(POut{gamma, out});
}

// round 12
// speedup vs baseline: 3.4475x; 1.0170x over previous
#include <cuda_runtime.h>

// Problem constants
#define B_   8
#define C_   512
#define L_   2048
#define CQ_  64
#define KK_  1536

typedef unsigned short u16;
typedef unsigned int   u32;

// ---------------------------------------------------------------------------
// Scratch (device globals — allocation-free). 16B-aligned for cp.async.
// ---------------------------------------------------------------------------
static __device__ __align__(16) u16 xsh_hi[3][B_ * C_ * L_];
static __device__ __align__(16) u16 xsh_lo[3][B_ * C_ * L_];
static __device__ __align__(16) u16 wqk_hi[3 * 128 * 512];   // [t][m][c], q|k rows
static __device__ __align__(16) u16 wqk_lo[3 * 128 * 512];
static __device__ __align__(16) u16 wv_hi[3 * 512 * 512];    // [t][m][c]
static __device__ __align__(16) u16 wv_lo[3 * 512 * 512];
static __device__ __align__(16) u16 q_hi[B_ * CQ_ * L_], q_lo[B_ * CQ_ * L_];
static __device__ __align__(16) u16 k_hi[B_ * CQ_ * L_], k_lo[B_ * CQ_ * L_];
static __device__ __align__(16) u16 v_hi[B_ * C_ * L_],  v_lo[B_ * C_ * L_];
static __device__ float g_s[B_ * L_ * L_];                   // scores (fp32)
static __device__ __align__(16) u16 b_hi[B_ * L_ * L_], b_lo[B_ * L_ * L_];

// SMEM buffer layout (per buffer):
//   A_hi @ 0      A_lo @ 10240    (NT: 128 rows x 80B; T: 32 rows x 272B)
//   B_hi @ 20480  B_lo @ 29184    (T: 32 k-rows x 272B)
#define SA_STRIDE 80u
#define ST_STRIDE 272u
#define OFF_ALO  10240u
#define OFF_BHI  20480u
#define OFF_BLO  29184u
#define BLO_DELTA 8704u          // OFF_BLO - OFF_BHI
#define BUF_SZ   37888u
#define SMEM_SZ  (2 * 37888)

// ---------------------------------------------------------------------------
// PTX helpers
// ---------------------------------------------------------------------------
static __device__ __forceinline__ void ldsm4(unsigned r[4], unsigned addr) {
    asm volatile("ldmatrix.sync.aligned.m8n8.x4.shared.b16 {%0,%1,%2,%3}, [%4];"
                 : "=r"(r[0]), "=r"(r[1]), "=r"(r[2]), "=r"(r[3]) : "r"(addr));
}
static __device__ __forceinline__ void ldsm4t(unsigned r[4], unsigned addr) {
    asm volatile("ldmatrix.sync.aligned.m8n8.x4.trans.shared.b16 {%0,%1,%2,%3}, [%4];"
                 : "=r"(r[0]), "=r"(r[1]), "=r"(r[2]), "=r"(r[3]) : "r"(addr));
}
static __device__ __forceinline__ void mma16816(float d[4], const unsigned a[4],
                                                unsigned b0, unsigned b1) {
    asm volatile(
        "mma.sync.aligned.m16n8k16.row.col.f32.bf16.bf16.f32 "
        "{%0,%1,%2,%3}, {%4,%5,%6,%7}, {%8,%9}, {%0,%1,%2,%3};"
        : "+f"(d[0]), "+f"(d[1]), "+f"(d[2]), "+f"(d[3])
        : "r"(a[0]), "r"(a[1]), "r"(a[2]), "r"(a[3]), "r"(b0), "r"(b1));
}
static __device__ __forceinline__ void cpa16(unsigned s, const void* g) {
    asm volatile("cp.async.cg.shared.global [%0], [%1], 16;" :: "r"(s), "l"(g));
}
#define CP_COMMIT() asm volatile("cp.async.commit_group;" ::: "memory")
static __device__ __forceinline__ void cp_wait1() {
    asm volatile("cp.async.wait_group 1;" ::: "memory");
}
static __device__ __forceinline__ void cp_wait0() {
    asm volatile("cp.async.wait_group 0;" ::: "memory");
}

// fp32 pair -> hi (top-16 truncation) + lo (rn bf16 of exact residual)
static __device__ __forceinline__ void split_pack(float a0, float a1, u32& h, u32& l) {
    u32 b0 = __float_as_uint(a0), b1 = __float_as_uint(a1);
    asm("prmt.b32 %0, %1, %2, 0x7632;" : "=r"(h) : "r"(b0), "r"(b1));
    float h0 = __uint_as_float(b0 & 0xffff0000u);
    float h1 = __uint_as_float(b1 & 0xffff0000u);
    asm("cvt.rn.bf16x2.f32 %0, %1, %2;" : "=r"(l) : "f"(a1 - h1), "f"(a0 - h0));
}
static __device__ __forceinline__ void pack8(const float* v, uint4& H, uint4& L) {
    u32 h[4], l[4];
#pragma unroll
    for (int i = 0; i < 4; i++) split_pack(v[2 * i], v[2 * i + 1], h[i], l[i]);
    H = make_uint4(h[0], h[1], h[2], h[3]);
    L = make_uint4(l[0], l[1], l[2], l[3]);
}
// fp32 pair -> (hi bf16x2 via rn, lo bf16x2 of residual)
static __device__ __forceinline__ void split_rn(float2 v, u32& h, u32& l) {
    asm("cvt.rn.bf16x2.f32 %0, %1, %2;" : "=r"(h) : "f"(v.y), "f"(v.x));
    float hx = __uint_as_float(h << 16);
    float hy = __uint_as_float(h & 0xffff0000u);
    asm("cvt.rn.bf16x2.f32 %0, %1, %2;" : "=r"(l) : "f"(v.y - hy), "f"(v.x - hx));
}

// ---------------------------------------------------------------------------
// Prep kernels
// ---------------------------------------------------------------------------
__global__ __launch_bounds__(256) void prep_x(const float* __restrict__ x)
{
    const int idx = blockIdx.x * 256 + threadIdx.x;      // over B*C*L/8
    const int base = idx * 8;
    const int row = base >> 11;                          // b*C + c
    const int l = base & (L_ - 1);
    const float* xr = x + (size_t)row * L_;

    float v[10];
    *(float4*)(v + 1) = *(const float4*)(xr + l);
    *(float4*)(v + 5) = *(const float4*)(xr + l + 4);
    v[0] = (l > 0) ? xr[l - 1] : 0.f;
    v[9] = (l + 8 < L_) ? xr[l + 8] : 0.f;

    const size_t o = (size_t)row * L_ + l;
#pragma unroll
    for (int t = 0; t < 3; t++) {        // xsh[t][j] = x[j + t - 1]
        uint4 H, L;
        pack8(v + t, H, L);
        *(uint4*)(&xsh_hi[t][o]) = H;
        *(uint4*)(&xsh_lo[t][o]) = L;
    }
}

__global__ __launch_bounds__(256) void prep_wqk(const float* __restrict__ Wq,
                                                const float* __restrict__ Wk)
{
    const int idx = blockIdx.x * 256 + threadIdx.x;      // 3*128*64
    const int c8 = idx & 63, m = (idx >> 6) & 127, t = idx >> 13;
    const float* src = ((m < CQ_) ? (Wq + m * KK_) : (Wk + (m - CQ_) * KK_)) + c8 * 24 + t;
    float v[8];
#pragma unroll
    for (int i = 0; i < 8; i++) v[i] = src[i * 3];
    uint4 H, L;
    pack8(v, H, L);
    const int o = (t * 128 + m) * 512 + c8 * 8;
    *(uint4*)(&wqk_hi[o]) = H;
    *(uint4*)(&wqk_lo[o]) = L;
}

__global__ __launch_bounds__(256) void prep_wv(const float* __restrict__ Wv)
{
    const int idx = blockIdx.x * 256 + threadIdx.x;      // 3*512*64
    const int c8 = idx & 63, m = (idx >> 6) & 511, t = idx >> 15;
    const float* src = Wv + m * KK_ + c8 * 24 + t;
    float v[8];
#pragma unroll
    for (int i = 0; i < 8; i++) v[i] = src[i * 3];
    uint4 H, L;
    pack8(v, H, L);
    const int o = (t * 512 + m) * 512 + c8 * 8;
    *(uint4*)(&wv_hi[o]) = H;
    *(uint4*)(&wv_lo[o]) = L;
}

// ---------------------------------------------------------------------------
// cp.async tile issue helpers
// ---------------------------------------------------------------------------
static __device__ __forceinline__ void cpA_NT(unsigned buf, int tid,
                                              const u16* hi, const u16* lo,
                                              size_t rstride) {
    const int m = tid >> 1, s = tid & 1;
    const unsigned sm = buf + (unsigned)m * SA_STRIDE + (unsigned)s * 32u;
    const size_t go = (size_t)m * rstride + s * 16;
    cpa16(sm,                 hi + go);  cpa16(sm + 16u,            hi + go + 8);
    cpa16(sm + OFF_ALO,       lo + go);  cpa16(sm + OFF_ALO + 16u,  lo + go + 8);
}
// ldelta = smem distance from hi tile to lo tile (A: OFF_ALO, B: BLO_DELTA).
static __device__ __forceinline__ void cpT(unsigned buf, int tid,
                                           const u16* hi, const u16* lo,
                                           size_t rstride, unsigned ldelta) {
    const int kc = tid >> 3, s = tid & 7;
    const unsigned sm = buf + (unsigned)kc * ST_STRIDE + (unsigned)s * 32u;
    const size_t go = (size_t)kc * rstride + s * 16;
    cpa16(sm,                hi + go);  cpa16(sm + 16u,           hi + go + 8);
    cpa16(sm + ldelta,       lo + go);  cpa16(sm + ldelta + 16u,  lo + go + 8);
}

// ---------------------------------------------------------------------------
// Per-problem structs
// ---------------------------------------------------------------------------
struct PConv {                   // merged conv: y=0..3 -> v rows, y=4 -> q|k rows
    static constexpr int NCH = 48;
    static constexpr bool A_T = false;
    __device__ void issue(unsigned buf, int ch, int tid) const {
        const int b = blockIdx.z, l0 = blockIdx.x * 128, y = blockIdx.y;
        const int t = ch >> 4, c0 = (ch & 15) * 32;
        const u16* Ah;
        const u16* Al;
        if (y == 4) {
            Ah = wqk_hi + (t * 128) * 512 + c0;
            Al = wqk_lo + (t * 128) * 512 + c0;
        } else {
            Ah = wv_hi + (t * 512 + y * 128) * 512 + c0;
            Al = wv_lo + (t * 512 + y * 128) * 512 + c0;
        }
        cpA_NT(buf, tid, Ah, Al, 512);
        const size_t bo = ((size_t)(b * C_ + c0)) * L_ + l0;
        cpT(buf + OFF_BHI, tid, xsh_hi[t] + bo, xsh_lo[t] + bo, L_, BLO_DELTA);
    }
    __device__ float scale() const { return 1.f; }
    __device__ void store2(int m, int col, float2 v) const {
        const int b = blockIdx.z, l0 = blockIdx.x * 128, y = blockIdx.y;
        u32 h, l;
        split_rn(v, h, l);
        if (y == 4) {
            const size_t off = ((size_t)(b * CQ_ + (m & 63))) * L_ + l0 + col;
            if (m < CQ_) { *(u32*)(q_hi + off) = h; *(u32*)(q_lo + off) = l; }
            else         { *(u32*)(k_hi + off) = h; *(u32*)(k_lo + off) = l; }
        } else {
            const size_t off = ((size_t)(b * C_ + y * 128 + m)) * L_ + l0 + col;
            *(u32*)(v_hi + off) = h;
            *(u32*)(v_lo + off) = l;
        }
    }
};

struct PScores {                 // D[i,j] = sum_c q[c,i]*k[c,j], K=64
    static constexpr int NCH = 2;
    static constexpr bool A_T = true;
    __device__ void issue(unsigned buf, int ch, int tid) const {
        const int b = blockIdx.z, j0 = blockIdx.x * 128, i0 = blockIdx.y * 128;
        const size_t ao = ((size_t)(b * CQ_ + ch * 32)) * L_ + i0;
        cpT(buf,           tid, q_hi + ao, q_lo + ao, L_, OFF_ALO);
        const size_t bo = ((size_t)(b * CQ_ + ch * 32)) * L_ + j0;
        cpT(buf + OFF_BHI, tid, k_hi + bo, k_lo + bo, L_, BLO_DELTA);
    }
    __device__ float scale() const { return 1.f; }
    __device__ void store2(int m, int col, float2 v) const {
        const int b = blockIdx.z, j0 = blockIdx.x * 128, i0 = blockIdx.y * 128;
        float* row = g_s + (size_t)b * L_ * L_ + (size_t)(i0 + m) * L_ + j0;
        *(float2*)(row + col) = v;
    }
};

struct POut {                    // out[c,j] = gamma * sum_l v[c,l]*beta[l,j], K=2048
    const float* gamma;
    float* out;
    static constexpr int NCH = 64;
    static constexpr bool A_T = false;
    __device__ void issue(unsigned buf, int ch, int tid) const {
        const int b = blockIdx.z, j0 = blockIdx.x * 128, c0 = blockIdx.y * 128;
        const size_t ao = ((size_t)(b * C_ + c0)) * L_ + ch * 32;
        cpA_NT(buf, tid, v_hi + ao, v_lo + ao, L_);
        const size_t bo = ((size_t)b * L_ + ch * 32) * L_ + j0;
        cpT(buf + OFF_BHI, tid, b_hi + bo, b_lo + bo, L_, BLO_DELTA);
    }
    __device__ float scale() const { return __ldg(gamma); }
    __device__ void store2(int m, int col, float2 v) const {
        const int b = blockIdx.z, j0 = blockIdx.x * 128, c0 = blockIdx.y * 128;
        float* row = out + ((size_t)(b * C_ + c0 + m)) * L_ + j0;
        *(float2*)(row + col) = v;
    }
};

// ---------------------------------------------------------------------------
// cp.async-pipelined mma.sync bf16-split GEMM core: 128x128 CTA tile, 8 warps,
// 64x32 warp tile, K-chunk 32, 3-term hi/lo split.
// ---------------------------------------------------------------------------
template <class P>
__global__ __launch_bounds__(256, 2) void mma_kernel(P prm)
{
    extern __shared__ __align__(16) char smem[];
    const unsigned sb = (unsigned)__cvta_generic_to_shared(smem);

    const int tid  = threadIdx.x;
    const int lane = tid & 31;
    const int wid  = tid >> 5;
    const int wm   = wid >> 2;
    const int wn   = wid & 3;

    float acc[4][4][4];
#pragma unroll
    for (int a = 0; a < 4; a++)
#pragma unroll
        for (int b = 0; b < 4; b++)
#pragma unroll
            for (int c = 0; c < 4; c++) acc[a][b][c] = 0.f;

    const unsigned mNT    = (unsigned)((lane & 7) + ((lane >> 3) & 1) * 8);
    const unsigned ksel   = (unsigned)((lane >> 4) & 1);
    const unsigned krowT  = (unsigned)(ksel * 8 + (lane & 7));
    const unsigned chalfT = (unsigned)(((lane >> 3) & 1) * 8);

    // Prologue: stage chunks 0 and 1.
    prm.issue(sb, 0, tid);
    CP_COMMIT();
    if (P::NCH > 1) { prm.issue(sb + BUF_SZ, 1, tid); CP_COMMIT(); cp_wait1(); }
    else cp_wait0();
    __syncthreads();

    for (int ch = 0; ch < P::NCH; ch++) {
        const unsigned base = sb + (unsigned)(ch & 1) * BUF_SZ;

#pragma unroll
        for (int ks = 0; ks < 2; ks++) {
            unsigned bh[2][4], bl[2][4];
            const unsigned kbB = ((unsigned)(ks * 16) + krowT) * ST_STRIDE;
#pragma unroll
            for (int n2 = 0; n2 < 2; n2++) {
                const unsigned col = ((unsigned)(wn * 32 + n2 * 16) + chalfT) * 2u;
                ldsm4t(bh[n2], base + OFF_BHI + kbB + col);
                ldsm4t(bl[n2], base + OFF_BLO + kbB + col);
            }
#pragma unroll
            for (int mi = 0; mi < 4; mi++) {
                unsigned ah4[4], al4[4];
                // Issue hi AND lo ldsm back-to-back: lo's latency hides under
                // the 16 hi-MMAs instead of stalling the final 8.
                if (P::A_T) {
                    const unsigned kb  = ((unsigned)(ks * 16) + krowT) * ST_STRIDE;
                    const unsigned col = ((unsigned)(wm * 64 + mi * 16) + chalfT) * 2u;
                    ldsm4t(ah4, base + kb + col);
                    ldsm4t(al4, base + OFF_ALO + kb + col);
                } else {
                    const unsigned row = (unsigned)(wm * 64 + mi * 16) + mNT;
                    const unsigned o   = row * SA_STRIDE + (unsigned)(ks * 32) + ksel * 16u;
                    ldsm4(ah4, base + o);
                    ldsm4(al4, base + OFF_ALO + o);
                }
#pragma unroll
                for (int n2 = 0; n2 < 2; n2++) {
                    mma16816(acc[mi][2 * n2],     ah4, bh[n2][0], bh[n2][2]);
                    mma16816(acc[mi][2 * n2 + 1], ah4, bh[n2][1], bh[n2][3]);
                    mma16816(acc[mi][2 * n2],     ah4, bl[n2][0], bl[n2][2]);
                    mma16816(acc[mi][2 * n2 + 1], ah4, bl[n2][1], bl[n2][3]);
                }
#pragma unroll
                for (int n2 = 0; n2 < 2; n2++) {
                    mma16816(acc[mi][2 * n2],     al4, bh[n2][0], bh[n2][2]);
                    mma16816(acc[mi][2 * n2 + 1], al4, bh[n2][1], bh[n2][3]);
                }
            }
        }

        __syncthreads();                    // all warps done reading buf[ch&1]
        if (ch + 2 < P::NCH) { prm.issue(base, ch + 2, tid); CP_COMMIT(); }
        if (ch + 1 < P::NCH) {
            if (ch + 2 < P::NCH) cp_wait1(); else cp_wait0();
            __syncthreads();                // buf[(ch+1)&1] fully landed
        }
    }

    const float s = prm.scale();
#pragma unroll
    for (int mi = 0; mi < 4; mi++) {
#pragma unroll
        for (int rr = 0; rr < 2; rr++) {
            const int r = wm * 64 + mi * 16 + (lane >> 2) + rr * 8;
#pragma unroll
            for (int ni = 0; ni < 4; ni++) {
                const int col = wn * 32 + ni * 8 + (lane & 3) * 2;
                float2 v;
                v.x = acc[mi][ni][2 * rr]     * s;
                v.y = acc[mi][ni][2 * rr + 1] * s;
                prm.store2(r, col, v);
            }
        }
    }
}

// ---------------------------------------------------------------------------
// Softmax over axis i of g_s[b, i, j]; writes beta as bf16 hi/lo.
// ---------------------------------------------------------------------------
__global__ __launch_bounds__(256) void softmax_kernel()
{
    __shared__ float redm[256];
    __shared__ float reds[256];

    const int b  = blockIdx.y;
    const int j0 = blockIdx.x * 32;
    const int tid = threadIdx.x;
    const int jj = tid & 31;
    const int ig = tid >> 5;

    const size_t cb = (size_t)b * L_ * L_ + j0 + jj;
    const float* sbp = g_s + cb;

    float m0 = -1e30f, s0 = 0.f, m1 = -1e30f, s1 = 0.f;
    for (int i = ig; i < L_; i += 16) {
        const float v0 = sbp[(size_t)i * L_];
        const float v1 = sbp[(size_t)(i + 8) * L_];
        float nm = fmaxf(m0, v0);
        s0 = s0 * __expf(m0 - nm) + __expf(v0 - nm);
        m0 = nm;
        nm = fmaxf(m1, v1);
        s1 = s1 * __expf(m1 - nm) + __expf(v1 - nm);
        m1 = nm;
    }
    {
        const float nm = fmaxf(m0, m1);
        s0 = s0 * __expf(m0 - nm) + s1 * __expf(m1 - nm);
        m0 = nm;
    }
    redm[tid] = m0;
    reds[tid] = s0;
    __syncthreads();

    float M = -1e30f, S = 0.f;
#pragma unroll
    for (int g = 0; g < 8; g++) {
        const float mm = redm[g * 32 + jj];
        const float ss = reds[g * 32 + jj];
        const float nm = fmaxf(M, mm);
        S = S * __expf(M - nm) + ss * __expf(mm - nm);
        M = nm;
    }
    const float inv = 1.f / S;

    for (int i = ig; i < L_; i += 16) {
#pragma unroll
        for (int u = 0; u < 2; u++) {
            const size_t idx = cb + (size_t)(i + u * 8) * L_;
            const float val = __expf(g_s[idx] - M) * inv;
            u16 hs;
            asm("cvt.rn.bf16.f32 %0, %1;" : "=h"(hs) : "f"(val));
            const float hf = __uint_as_float((u32)hs << 16);
            u16 ls;
            asm("cvt.rn.bf16.f32 %0, %1;" : "=h"(ls) : "f"(val - hf));
            b_hi[idx] = hs;
            b_lo[idx] = ls;
        }
    }
}

// ---------------------------------------------------------------------------
extern "C" void kernel_launch(void* const* d_in, const int* in_sizes, int n_in,
                              void* d_out, int out_size)
{
    const float* x     = (const float*)d_in[0];
    const float* Wq    = (const float*)d_in[1];
    const float* Wk    = (const float*)d_in[2];
    const float* Wv    = (const float*)d_in[3];
    const float* gamma = (const float*)d_in[4];
    float* out = (float*)d_out;

    cudaFuncSetAttribute(mma_kernel<PConv>,
                         cudaFuncAttributeMaxDynamicSharedMemorySize, SMEM_SZ);
    cudaFuncSetAttribute(mma_kernel<PScores>,
                         cudaFuncAttributeMaxDynamicSharedMemorySize, SMEM_SZ);
    cudaFuncSetAttribute(mma_kernel<POut>,
                         cudaFuncAttributeMaxDynamicSharedMemorySize, SMEM_SZ);

    dim3 blk(256);

    prep_x  <<<B_ * C_ * L_ / 8 / 256, blk>>>(x);
    prep_wqk<<<3 * 128 * 64 / 256,     blk>>>(Wq, Wk);
    prep_wv <<<3 * 512 * 64 / 256,     blk>>>(Wv);

    mma_kernel<PConv>  <<<dim3(L_ / 128, 5, B_),        blk, SMEM_SZ>>>(PConv{});
    mma_kernel<PScores><<<dim3(L_ / 128, L_ / 128, B_), blk, SMEM_SZ>>>(PScores{});
    softmax_kernel     <<<dim3(L_ / 32, B_),            blk>>>();
    mma_kernel<POut>   <<<dim3(L_ / 128, C_ / 128, B_), blk, SMEM_SZ>>>(POut{gamma, out});
}

// round 13
// speedup vs baseline: 3.6131x; 1.0480x over previous
#include <cuda_runtime.h>

// Problem constants
#define B_   8
#define C_   512
#define L_   2048
#define CQ_  64
#define KK_  1536

typedef unsigned short u16;
typedef unsigned int   u32;

// ---------------------------------------------------------------------------
// Scratch (device globals — allocation-free). 16B-aligned for cp.async.
// ---------------------------------------------------------------------------
static __device__ __align__(16) u16 xsh_hi[3][B_ * C_ * L_];
static __device__ __align__(16) u16 xsh_lo[3][B_ * C_ * L_];
static __device__ __align__(16) u16 wqk_hi[3 * 128 * 512];   // [t][m][c], q|k rows
static __device__ __align__(16) u16 wqk_lo[3 * 128 * 512];
static __device__ __align__(16) u16 wv_hi[3 * 512 * 512];    // [t][m][c]
static __device__ __align__(16) u16 wv_lo[3 * 512 * 512];
static __device__ __align__(16) u16 q_hi[B_ * CQ_ * L_], q_lo[B_ * CQ_ * L_];
static __device__ __align__(16) u16 k_hi[B_ * CQ_ * L_], k_lo[B_ * CQ_ * L_];
static __device__ __align__(16) u16 v_hi[B_ * C_ * L_],  v_lo[B_ * C_ * L_];
static __device__ float g_s[B_ * L_ * L_];                   // scores (fp32)
static __device__ __align__(16) u16 b_hi[B_ * L_ * L_], b_lo[B_ * L_ * L_];

// SMEM stage layout (per stage):
//   A_hi @ 0      A_lo @ 10240    (NT: 128 rows x 80B; T: 32 rows x 272B)
//   B_hi @ 20480  B_lo @ 29184    (T: 32 k-rows x 272B)
#define SA_STRIDE 80u
#define ST_STRIDE 272u
#define OFF_ALO  10240u
#define OFF_BHI  20480u
#define OFF_BLO  29184u
#define BLO_DELTA 8704u          // OFF_BLO - OFF_BHI
#define BUF_SZ   37888u
#define NSTAGE   3
#define SMEM_SZ  (NSTAGE * 37888)   // 113664 B/CTA -> 2 CTAs = 227.3KB/SM

// ---------------------------------------------------------------------------
// PTX helpers
// ---------------------------------------------------------------------------
static __device__ __forceinline__ void ldsm4(unsigned r[4], unsigned addr) {
    asm volatile("ldmatrix.sync.aligned.m8n8.x4.shared.b16 {%0,%1,%2,%3}, [%4];"
                 : "=r"(r[0]), "=r"(r[1]), "=r"(r[2]), "=r"(r[3]) : "r"(addr));
}
static __device__ __forceinline__ void ldsm4t(unsigned r[4], unsigned addr) {
    asm volatile("ldmatrix.sync.aligned.m8n8.x4.trans.shared.b16 {%0,%1,%2,%3}, [%4];"
                 : "=r"(r[0]), "=r"(r[1]), "=r"(r[2]), "=r"(r[3]) : "r"(addr));
}
static __device__ __forceinline__ void mma16816(float d[4], const unsigned a[4],
                                                unsigned b0, unsigned b1) {
    asm volatile(
        "mma.sync.aligned.m16n8k16.row.col.f32.bf16.bf16.f32 "
        "{%0,%1,%2,%3}, {%4,%5,%6,%7}, {%8,%9}, {%0,%1,%2,%3};"
        : "+f"(d[0]), "+f"(d[1]), "+f"(d[2]), "+f"(d[3])
        : "r"(a[0]), "r"(a[1]), "r"(a[2]), "r"(a[3]), "r"(b0), "r"(b1));
}
static __device__ __forceinline__ void cpa16(unsigned s, const void* g) {
    asm volatile("cp.async.cg.shared.global [%0], [%1], 16;" :: "r"(s), "l"(g));
}
#define CP_COMMIT() asm volatile("cp.async.commit_group;" ::: "memory")
static __device__ __forceinline__ void cp_wait1() {
    asm volatile("cp.async.wait_group 1;" ::: "memory");
}

// fp32 pair -> hi (top-16 truncation) + lo (rn bf16 of exact residual)
static __device__ __forceinline__ void split_pack(float a0, float a1, u32& h, u32& l) {
    u32 b0 = __float_as_uint(a0), b1 = __float_as_uint(a1);
    asm("prmt.b32 %0, %1, %2, 0x7632;" : "=r"(h) : "r"(b0), "r"(b1));
    float h0 = __uint_as_float(b0 & 0xffff0000u);
    float h1 = __uint_as_float(b1 & 0xffff0000u);
    asm("cvt.rn.bf16x2.f32 %0, %1, %2;" : "=r"(l) : "f"(a1 - h1), "f"(a0 - h0));
}
static __device__ __forceinline__ void pack8(const float* v, uint4& H, uint4& L) {
    u32 h[4], l[4];
#pragma unroll
    for (int i = 0; i < 4; i++) split_pack(v[2 * i], v[2 * i + 1], h[i], l[i]);
    H = make_uint4(h[0], h[1], h[2], h[3]);
    L = make_uint4(l[0], l[1], l[2], l[3]);
}
static __device__ __forceinline__ void split_rn(float2 v, u32& h, u32& l) {
    asm("cvt.rn.bf16x2.f32 %0, %1, %2;" : "=r"(h) : "f"(v.y), "f"(v.x));
    float hx = __uint_as_float(h << 16);
    float hy = __uint_as_float(h & 0xffff0000u);
    asm("cvt.rn.bf16x2.f32 %0, %1, %2;" : "=r"(l) : "f"(v.y - hy), "f"(v.x - hx));
}

// ---------------------------------------------------------------------------
// Prep kernels
// ---------------------------------------------------------------------------
__global__ __launch_bounds__(256) void prep_x(const float* __restrict__ x)
{
    const int idx = blockIdx.x * 256 + threadIdx.x;      // over B*C*L/8
    const int base = idx * 8;
    const int row = base >> 11;                          // b*C + c
    const int l = base & (L_ - 1);
    const float* xr = x + (size_t)row * L_;

    float v[10];
    *(float4*)(v + 1) = *(const float4*)(xr + l);
    *(float4*)(v + 5) = *(const float4*)(xr + l + 4);
    v[0] = (l > 0) ? xr[l - 1] : 0.f;
    v[9] = (l + 8 < L_) ? xr[l + 8] : 0.f;

    const size_t o = (size_t)row * L_ + l;
#pragma unroll
    for (int t = 0; t < 3; t++) {        // xsh[t][j] = x[j + t - 1]
        uint4 H, L;
        pack8(v + t, H, L);
        *(uint4*)(&xsh_hi[t][o]) = H;
        *(uint4*)(&xsh_lo[t][o]) = L;
    }
}

__global__ __launch_bounds__(256) void prep_wqk(const float* __restrict__ Wq,
                                                const float* __restrict__ Wk)
{
    const int idx = blockIdx.x * 256 + threadIdx.x;      // 3*128*64
    const int c8 = idx & 63, m = (idx >> 6) & 127, t = idx >> 13;
    const float* src = ((m < CQ_) ? (Wq + m * KK_) : (Wk + (m - CQ_) * KK_)) + c8 * 24 + t;
    float v[8];
#pragma unroll
    for (int i = 0; i < 8; i++) v[i] = src[i * 3];
    uint4 H, L;
    pack8(v, H, L);
    const int o = (t * 128 + m) * 512 + c8 * 8;
    *(uint4*)(&wqk_hi[o]) = H;
    *(uint4*)(&wqk_lo[o]) = L;
}

__global__ __launch_bounds__(256) void prep_wv(const float* __restrict__ Wv)
{
    const int idx = blockIdx.x * 256 + threadIdx.x;      // 3*512*64
    const int c8 = idx & 63, m = (idx >> 6) & 511, t = idx >> 15;
    const float* src = Wv + m * KK_ + c8 * 24 + t;
    float v[8];
#pragma unroll
    for (int i = 0; i < 8; i++) v[i] = src[i * 3];
    uint4 H, L;
    pack8(v, H, L);
    const int o = (t * 512 + m) * 512 + c8 * 8;
    *(uint4*)(&wv_hi[o]) = H;
    *(uint4*)(&wv_lo[o]) = L;
}

// ---------------------------------------------------------------------------
// cp.async tile issue helpers
// ---------------------------------------------------------------------------
static __device__ __forceinline__ void cpA_NT(unsigned buf, int tid,
                                              const u16* hi, const u16* lo,
                                              size_t rstride) {
    const int m = tid >> 1, s = tid & 1;
    const unsigned sm = buf + (unsigned)m * SA_STRIDE + (unsigned)s * 32u;
    const size_t go = (size_t)m * rstride + s * 16;
    cpa16(sm,                 hi + go);  cpa16(sm + 16u,            hi + go + 8);
    cpa16(sm + OFF_ALO,       lo + go);  cpa16(sm + OFF_ALO + 16u,  lo + go + 8);
}
// ldelta = smem distance from hi tile to lo tile (A: OFF_ALO, B: BLO_DELTA).
static __device__ __forceinline__ void cpT(unsigned buf, int tid,
                                           const u16* hi, const u16* lo,
                                           size_t rstride, unsigned ldelta) {
    const int kc = tid >> 3, s = tid & 7;
    const unsigned sm = buf + (unsigned)kc * ST_STRIDE + (unsigned)s * 32u;
    const size_t go = (size_t)kc * rstride + s * 16;
    cpa16(sm,                hi + go);  cpa16(sm + 16u,           hi + go + 8);
    cpa16(sm + ldelta,       lo + go);  cpa16(sm + ldelta + 16u,  lo + go + 8);
}

// ---------------------------------------------------------------------------
// Per-problem structs
// ---------------------------------------------------------------------------
struct PConv {                   // merged conv: y=0..3 -> v rows, y=4 -> q|k rows
    static constexpr int NCH = 48;
    static constexpr bool A_T = false;
    __device__ void issue(unsigned buf, int ch, int tid) const {
        const int b = blockIdx.z, l0 = blockIdx.x * 128, y = blockIdx.y;
        const int t = ch >> 4, c0 = (ch & 15) * 32;
        const u16* Ah;
        const u16* Al;
        if (y == 4) {
            Ah = wqk_hi + (t * 128) * 512 + c0;
            Al = wqk_lo + (t * 128) * 512 + c0;
        } else {
            Ah = wv_hi + (t * 512 + y * 128) * 512 + c0;
            Al = wv_lo + (t * 512 + y * 128) * 512 + c0;
        }
        cpA_NT(buf, tid, Ah, Al, 512);
        const size_t bo = ((size_t)(b * C_ + c0)) * L_ + l0;
        cpT(buf + OFF_BHI, tid, xsh_hi[t] + bo, xsh_lo[t] + bo, L_, BLO_DELTA);
    }
    __device__ float scale() const { return 1.f; }
    __device__ void store2(int m, int col, float2 v) const {
        const int b = blockIdx.z, l0 = blockIdx.x * 128, y = blockIdx.y;
        u32 h, l;
        split_rn(v, h, l);
        if (y == 4) {
            const size_t off = ((size_t)(b * CQ_ + (m & 63))) * L_ + l0 + col;
            if (m < CQ_) { *(u32*)(q_hi + off) = h; *(u32*)(q_lo + off) = l; }
            else         { *(u32*)(k_hi + off) = h; *(u32*)(k_lo + off) = l; }
        } else {
            const size_t off = ((size_t)(b * C_ + y * 128 + m)) * L_ + l0 + col;
            *(u32*)(v_hi + off) = h;
            *(u32*)(v_lo + off) = l;
        }
    }
};

struct PScores {                 // D[i,j] = sum_c q[c,i]*k[c,j], K=64
    static constexpr int NCH = 2;
    static constexpr bool A_T = true;
    __device__ void issue(unsigned buf, int ch, int tid) const {
        const int b = blockIdx.z, j0 = blockIdx.x * 128, i0 = blockIdx.y * 128;
        const size_t ao = ((size_t)(b * CQ_ + ch * 32)) * L_ + i0;
        cpT(buf,           tid, q_hi + ao, q_lo + ao, L_, OFF_ALO);
        const size_t bo = ((size_t)(b * CQ_ + ch * 32)) * L_ + j0;
        cpT(buf + OFF_BHI, tid, k_hi + bo, k_lo + bo, L_, BLO_DELTA);
    }
    __device__ float scale() const { return 1.f; }
    __device__ void store2(int m, int col, float2 v) const {
        const int b = blockIdx.z, j0 = blockIdx.x * 128, i0 = blockIdx.y * 128;
        float* row = g_s + (size_t)b * L_ * L_ + (size_t)(i0 + m) * L_ + j0;
        *(float2*)(row + col) = v;
    }
};

struct POut {                    // out[c,j] = gamma * sum_l v[c,l]*beta[l,j], K=2048
    const float* gamma;
    float* out;
    static constexpr int NCH = 64;
    static constexpr bool A_T = false;
    __device__ void issue(unsigned buf, int ch, int tid) const {
        const int b = blockIdx.z, j0 = blockIdx.x * 128, c0 = blockIdx.y * 128;
        const size_t ao = ((size_t)(b * C_ + c0)) * L_ + ch * 32;
        cpA_NT(buf, tid, v_hi + ao, v_lo + ao, L_);
        const size_t bo = ((size_t)b * L_ + ch * 32) * L_ + j0;
        cpT(buf + OFF_BHI, tid, b_hi + bo, b_lo + bo, L_, BLO_DELTA);
    }
    __device__ float scale() const { return __ldg(gamma); }
    __device__ void store2(int m, int col, float2 v) const {
        const int b = blockIdx.z, j0 = blockIdx.x * 128, c0 = blockIdx.y * 128;
        float* row = out + ((size_t)(b * C_ + c0 + m)) * L_ + j0;
        *(float2*)(row + col) = v;
    }
};

// ---------------------------------------------------------------------------
// 3-stage cp.async pipeline, ONE barrier per chunk. 128x128 CTA tile, 8 warps,
// 64x32 warp tile, K-chunk 32, 3-term hi/lo split, distance-4 acc ordering.
// ---------------------------------------------------------------------------
template <class P>
__global__ __launch_bounds__(256, 2) void mma_kernel(P prm)
{
    extern __shared__ __align__(16) char smem[];
    const unsigned sb = (unsigned)__cvta_generic_to_shared(smem);

    const int tid  = threadIdx.x;
    const int lane = tid & 31;
    const int wid  = tid >> 5;
    const int wm   = wid >> 2;
    const int wn   = wid & 3;

    float acc[4][4][4];
#pragma unroll
    for (int a = 0; a < 4; a++)
#pragma unroll
        for (int b = 0; b < 4; b++)
#pragma unroll
            for (int c = 0; c < 4; c++) acc[a][b][c] = 0.f;

    const unsigned mNT    = (unsigned)((lane & 7) + ((lane >> 3) & 1) * 8);
    const unsigned ksel   = (unsigned)((lane >> 4) & 1);
    const unsigned krowT  = (unsigned)(ksel * 8 + (lane & 7));
    const unsigned chalfT = (unsigned)(((lane >> 3) & 1) * 8);

    // Prologue: stage chunks 0 and 1 (one commit-group each).
    prm.issue(sb, 0, tid);
    CP_COMMIT();
    if (P::NCH > 1) prm.issue(sb + BUF_SZ, 1, tid);
    CP_COMMIT();

    int stage = 0;                       // ch % NSTAGE
    int wstage = 2;                      // (ch+2) % NSTAGE
    for (int ch = 0; ch < P::NCH; ch++) {
        cp_wait1();                      // oldest pending group (chunk ch) landed
        __syncthreads();                 // also: all warps done reading buf[wstage]

        const unsigned base = sb + (unsigned)stage * BUF_SZ;

#pragma unroll
        for (int ks = 0; ks < 2; ks++) {
            unsigned bh[2][4], bl[2][4];
            const unsigned kbB = ((unsigned)(ks * 16) + krowT) * ST_STRIDE;
#pragma unroll
            for (int n2 = 0; n2 < 2; n2++) {
                const unsigned col = ((unsigned)(wn * 32 + n2 * 16) + chalfT) * 2u;
                ldsm4t(bh[n2], base + OFF_BHI + kbB + col);
                ldsm4t(bl[n2], base + OFF_BLO + kbB + col);
            }
#pragma unroll
            for (int mi = 0; mi < 4; mi++) {
                unsigned ah4[4], al4[4];
                if (P::A_T) {
                    const unsigned kb  = ((unsigned)(ks * 16) + krowT) * ST_STRIDE;
                    const unsigned col = ((unsigned)(wm * 64 + mi * 16) + chalfT) * 2u;
                    ldsm4t(ah4, base + kb + col);
                    ldsm4t(al4, base + OFF_ALO + kb + col);
                } else {
                    const unsigned row = (unsigned)(wm * 64 + mi * 16) + mNT;
                    const unsigned o   = row * SA_STRIDE + (unsigned)(ks * 32) + ksel * 16u;
                    ldsm4(ah4, base + o);
                    ldsm4(al4, base + OFF_ALO + o);
                }
                // hh: acc0..3, then hl: acc0..3, then lh: acc0..3
                // -> same-acc distance 4 (32 cyc at rt=8) >= HMMA latency.
                mma16816(acc[mi][0], ah4, bh[0][0], bh[0][2]);
                mma16816(acc[mi][1], ah4, bh[0][1], bh[0][3]);
                mma16816(acc[mi][2], ah4, bh[1][0], bh[1][2]);
                mma16816(acc[mi][3], ah4, bh[1][1], bh[1][3]);

                mma16816(acc[mi][0], ah4, bl[0][0], bl[0][2]);
                mma16816(acc[mi][1], ah4, bl[0][1], bl[0][3]);
                mma16816(acc[mi][2], ah4, bl[1][0], bl[1][2]);
                mma16816(acc[mi][3], ah4, bl[1][1], bl[1][3]);

                mma16816(acc[mi][0], al4, bh[0][0], bh[0][2]);
                mma16816(acc[mi][1], al4, bh[0][1], bh[0][3]);
                mma16816(acc[mi][2], al4, bh[1][0], bh[1][2]);
                mma16816(acc[mi][3], al4, bh[1][1], bh[1][3]);
            }
        }

        // Stage chunk ch+2 into buf[wstage] (freed by this iteration's barrier).
        if (ch + 2 < P::NCH)
            prm.issue(sb + (unsigned)wstage * BUF_SZ, ch + 2, tid);
        CP_COMMIT();                     // empty group when nothing issued

        stage  = (stage  == NSTAGE - 1) ? 0 : stage + 1;
        wstage = (wstage == NSTAGE - 1) ? 0 : wstage + 1;
    }

    const float s = prm.scale();
#pragma unroll
    for (int mi = 0; mi < 4; mi++) {
#pragma unroll
        for (int rr = 0; rr < 2; rr++) {
            const int r = wm * 64 + mi * 16 + (lane >> 2) + rr * 8;
#pragma unroll
            for (int ni = 0; ni < 4; ni++) {
                const int col = wn * 32 + ni * 8 + (lane & 3) * 2;
                float2 v;
                v.x = acc[mi][ni][2 * rr]     * s;
                v.y = acc[mi][ni][2 * rr + 1] * s;
                prm.store2(r, col, v);
            }
        }
    }
}

// ---------------------------------------------------------------------------
// Softmax over axis i of g_s[b, i, j]; writes beta as bf16 hi/lo.
// ---------------------------------------------------------------------------
__global__ __launch_bounds__(256) void softmax_kernel()
{
    __shared__ float redm[256];
    __shared__ float reds[256];

    const int b  = blockIdx.y;
    const int j0 = blockIdx.x * 32;
    const int tid = threadIdx.x;
    const int jj = tid & 31;
    const int ig = tid >> 5;

    const size_t cb = (size_t)b * L_ * L_ + j0 + jj;
    const float* sbp = g_s + cb;

    float m0 = -1e30f, s0 = 0.f, m1 = -1e30f, s1 = 0.f;
    for (int i = ig; i < L_; i += 16) {
        const float v0 = sbp[(size_t)i * L_];
        const float v1 = sbp[(size_t)(i + 8) * L_];
        float nm = fmaxf(m0, v0);
        s0 = s0 * __expf(m0 - nm) + __expf(v0 - nm);
        m0 = nm;
        nm = fmaxf(m1, v1);
        s1 = s1 * __expf(m1 - nm) + __expf(v1 - nm);
        m1 = nm;
    }
    {
        const float nm = fmaxf(m0, m1);
        s0 = s0 * __expf(m0 - nm) + s1 * __expf(m1 - nm);
        m0 = nm;
    }
    redm[tid] = m0;
    reds[tid] = s0;
    __syncthreads();

    float M = -1e30f, S = 0.f;
#pragma unroll
    for (int g = 0; g < 8; g++) {
        const float mm = redm[g * 32 + jj];
        const float ss = reds[g * 32 + jj];
        const float nm = fmaxf(M, mm);
        S = S * __expf(M - nm) + ss * __expf(mm - nm);
        M = nm;
    }
    const float inv = 1.f / S;

    for (int i = ig; i < L_; i += 16) {
#pragma unroll
        for (int u = 0; u < 2; u++) {
            const size_t idx = cb + (size_t)(i + u * 8) * L_;
            const float val = __expf(g_s[idx] - M) * inv;
            u16 hs;
            asm("cvt.rn.bf16.f32 %0, %1;" : "=h"(hs) : "f"(val));
            const float hf = __uint_as_float((u32)hs << 16);
            u16 ls;
            asm("cvt.rn.bf16.f32 %0, %1;" : "=h"(ls) : "f"(val - hf));
            b_hi[idx] = hs;
            b_lo[idx] = ls;
        }
    }
}

// ---------------------------------------------------------------------------
extern "C" void kernel_launch(void* const* d_in, const int* in_sizes, int n_in,
                              void* d_out, int out_size)
{
    const float* x     = (const float*)d_in[0];
    const float* Wq    = (const float*)d_in[1];
    const float* Wk    = (const float*)d_in[2];
    const float* Wv    = (const float*)d_in[3];
    const float* gamma = (const float*)d_in[4];
    float* out = (float*)d_out;

    cudaFuncSetAttribute(mma_kernel<PConv>,
                         cudaFuncAttributeMaxDynamicSharedMemorySize, SMEM_SZ);
    cudaFuncSetAttribute(mma_kernel<PScores>,
                         cudaFuncAttributeMaxDynamicSharedMemorySize, SMEM_SZ);
    cudaFuncSetAttribute(mma_kernel<POut>,
                         cudaFuncAttributeMaxDynamicSharedMemorySize, SMEM_SZ);

    dim3 blk(256);

    prep_x  <<<B_ * C_ * L_ / 8 / 256, blk>>>(x);
    prep_wqk<<<3 * 128 * 64 / 256,     blk>>>(Wq, Wk);
    prep_wv <<<3 * 512 * 64 / 256,     blk>>>(Wv);

    mma_kernel<PConv>  <<<dim3(L_ / 128, 5, B_),        blk, SMEM_SZ>>>(PConv{});
    mma_kernel<PScores><<<dim3(L_ / 128, L_ / 128, B_), blk, SMEM_SZ>>>(PScores{});
    softmax_kernel     <<<dim3(L_ / 32, B_),            blk>>>();
    mma_kernel<POut>   <<<dim3(L_ / 128, C_ / 128, B_), blk, SMEM_SZ>>>(POut{gamma, out});
}